// round 4
// baseline (speedup 1.0000x reference)
#include <cuda_runtime.h>
#include <cuda_bf16.h>

// Problem constants
#define B_ 8
#define H_ 64
#define W_ 64
#define C_ 256
#define NPIXTOT (B_*H_*W_)

// Scratch buffers (device globals; no allocation allowed)
__device__ float g_qcat[NPIXTOT * C_];
__device__ float g_q[NPIXTOT * C_];
__device__ float g_k1[NPIXTOT * C_];
__device__ float g_k[NPIXTOT * C_];
__device__ float g_v[NPIXTOT * C_];
__device__ float g_energy[NPIXTOT * C_];
__device__ float g_attnT[NPIXTOT * C_];

// ---------------------------------------------------------------------------
// Generic direct conv (KSxKS, dilation DIL, Cin=256, SAME zero padding).
// NHWC input, HWIO weights. Block = 256 threads.
// Thread handles 4 consecutive couts (float4 weights) x NPIX pixels.
// ---------------------------------------------------------------------------
template<int COUT, int KS, int DIL>
__global__ __launch_bounds__(256)
void conv_kernel(const float* __restrict__ x, const float* __restrict__ w,
                 const float* __restrict__ bias, float* __restrict__ out,
                 int coff, int ctot)
{
    constexpr int TW  = (COUT == 256) ? 32 : 64;   // pixel tile (within one row)
    constexpr int CC  = (COUT == 256) ? 32 : 64;   // cin chunk
    constexpr int NQ  = COUT / 4;                  // cout quads
    constexpr int NG  = 256 / NQ;                  // pixel groups
    constexpr int NPIX = TW / NG;                  // pixels per thread

    __shared__ float ws[CC * COUT];
    __shared__ float xs[TW * CC];

    const int tid  = threadIdx.x;
    const int q    = tid % NQ;
    const int g    = tid / NQ;
    const int cout = q * 4;
    const int w0   = blockIdx.x * TW;
    const int h    = blockIdx.y;
    const int b    = blockIdx.z;

    float acc[NPIX][4];
    {
        const float4 bb = *(const float4*)&bias[cout];
        #pragma unroll
        for (int p = 0; p < NPIX; p++) {
            acc[p][0] = bb.x; acc[p][1] = bb.y; acc[p][2] = bb.z; acc[p][3] = bb.w;
        }
    }

    for (int ky = 0; ky < KS; ky++) {
        const int h_in = h + (ky - KS/2) * DIL;
        if (h_in < 0 || h_in >= H_) continue;   // uniform across block
        for (int kx = 0; kx < KS; kx++) {
            const int dwx = (kx - KS/2) * DIL;
            for (int c0 = 0; c0 < C_; c0 += CC) {
                // load weight chunk ws[cin][cout]
                #pragma unroll
                for (int idx = tid * 4; idx < CC * COUT; idx += 256 * 4) {
                    const int ci = idx / COUT;
                    const int co = idx % COUT;
                    *(float4*)&ws[idx] =
                        *(const float4*)&w[(((ky*KS + kx)*C_ + c0 + ci) * COUT) + co];
                }
                // load input chunk xs[pixel][cin] (zero pad OOB)
                #pragma unroll
                for (int idx = tid * 4; idx < TW * CC; idx += 256 * 4) {
                    const int p    = idx / CC;
                    const int ci   = idx % CC;
                    const int w_in = w0 + p + dwx;
                    float4 v4 = make_float4(0.f, 0.f, 0.f, 0.f);
                    if (w_in >= 0 && w_in < W_)
                        v4 = *(const float4*)&x[(((b*H_ + h_in)*W_ + w_in) * C_) + c0 + ci];
                    *(float4*)&xs[idx] = v4;
                }
                __syncthreads();
                #pragma unroll 4
                for (int ci = 0; ci < CC; ci++) {
                    const float4 wv = *(const float4*)&ws[ci * COUT + cout];
                    #pragma unroll
                    for (int p = 0; p < NPIX; p++) {
                        const float xv = xs[(g * NPIX + p) * CC + ci];
                        acc[p][0] = fmaf(xv, wv.x, acc[p][0]);
                        acc[p][1] = fmaf(xv, wv.y, acc[p][1]);
                        acc[p][2] = fmaf(xv, wv.z, acc[p][2]);
                        acc[p][3] = fmaf(xv, wv.w, acc[p][3]);
                    }
                }
                __syncthreads();
            }
        }
    }

    #pragma unroll
    for (int p = 0; p < NPIX; p++) {
        const int pw = w0 + g * NPIX + p;
        float* o = &out[(((b*H_ + h)*W_ + pw) * ctot) + coff + cout];
        *(float4*)o = make_float4(acc[p][0], acc[p][1], acc[p][2], acc[p][3]);
    }
}

// ---------------------------------------------------------------------------
// Per-channel spatial "matmul": acc[i,k,c] = sum_j A[b,i,j,c] * Brow(j,k)[c]
// SWAPB=true : Brow = Bm[b, j, k0+r, :]   (energy: q accessed transposed)
// SWAPB=false: Brow = Bm[b, k0+r, j, :]   (output: v)
// FUSE: out = gamma*acc + x  (final result), else out = acc (energy)
// Block: 256 threads (one per channel). 8x8 spatial tile per block.
// ---------------------------------------------------------------------------
template<bool SWAPB, bool FUSE>
__global__ __launch_bounds__(256)
void pairmm_kernel(const float* __restrict__ A, const float* __restrict__ Bm,
                   float* __restrict__ out, const float* __restrict__ x,
                   const float* __restrict__ gammap)
{
    __shared__ float As[8 * 256];
    __shared__ float Bs[8 * 256];

    const int c  = threadIdx.x;
    const int i0 = blockIdx.x * 8;
    const int k0 = blockIdx.y * 8;
    const int b  = blockIdx.z;

    float acc[8][8];
    #pragma unroll
    for (int ii = 0; ii < 8; ii++)
        #pragma unroll
        for (int kk = 0; kk < 8; kk++) acc[ii][kk] = 0.f;

    for (int j = 0; j < 64; j++) {
        #pragma unroll
        for (int r = 0; r < 8; r++) {
            As[r*256 + c] = A[(((b*64 + i0 + r)*64 + j) * 256) + c];
            const int brow = SWAPB ? ((b*64 + j)*64 + (k0 + r))
                                   : ((b*64 + (k0 + r))*64 + j);
            Bs[r*256 + c] = Bm[brow * 256 + c];
        }
        __syncthreads();
        float bv[8];
        #pragma unroll
        for (int kk = 0; kk < 8; kk++) bv[kk] = Bs[kk*256 + c];
        #pragma unroll
        for (int ii = 0; ii < 8; ii++) {
            const float av = As[ii*256 + c];
            #pragma unroll
            for (int kk = 0; kk < 8; kk++)
                acc[ii][kk] = fmaf(av, bv[kk], acc[ii][kk]);
        }
        __syncthreads();
    }

    const float gm = FUSE ? gammap[0] : 0.f;
    #pragma unroll
    for (int ii = 0; ii < 8; ii++) {
        #pragma unroll
        for (int kk = 0; kk < 8; kk++) {
            const int idx = (((b*64 + i0 + ii)*64 + (k0 + kk)) * 256) + c;
            if (FUSE) out[idx] = gm * acc[ii][kk] + x[idx];
            else      out[idx] = acc[ii][kk];
        }
    }
}

// ---------------------------------------------------------------------------
// Softmax over channel axis (C=256) with transposed spatial write:
// attnT[b, i, j, :] = softmax_c( energy[b, j, i, :] )
// One warp per row; 8 rows per 256-thread block.
// ---------------------------------------------------------------------------
__global__ __launch_bounds__(256)
void softmax_t_kernel(const float* __restrict__ e, float* __restrict__ at)
{
    const int warp = threadIdx.x / 32;
    const int lane = threadIdx.x % 32;
    const int row  = blockIdx.x * 8 + warp;          // (b*64 + j)*64 + i

    const float* er = &e[row * 256];
    float v[8];
    float m = -1e30f;
    #pragma unroll
    for (int s = 0; s < 8; s++) { v[s] = er[lane + 32*s]; m = fmaxf(m, v[s]); }
    #pragma unroll
    for (int o = 16; o; o >>= 1) m = fmaxf(m, __shfl_xor_sync(0xffffffffu, m, o));
    float sum = 0.f;
    #pragma unroll
    for (int s = 0; s < 8; s++) { v[s] = __expf(v[s] - m); sum += v[s]; }
    #pragma unroll
    for (int o = 16; o; o >>= 1) sum += __shfl_xor_sync(0xffffffffu, sum, o);
    const float inv = 1.0f / sum;

    const int ii  = row % 64;
    const int bjj = row / 64;
    const int jj  = bjj % 64;
    const int b   = bjj / 64;
    float* orow = &at[((b*64 + ii)*64 + jj) * 256];
    #pragma unroll
    for (int s = 0; s < 8; s++) orow[lane + 32*s] = v[s] * inv;
}

// ---------------------------------------------------------------------------
extern "C" void kernel_launch(void* const* d_in, const int* in_sizes, int n_in,
                              void* d_out, int out_size)
{
    const float* x    = (const float*)d_in[0];
    const float* wq   = (const float*)d_in[1];
    const float* bq   = (const float*)d_in[2];
    const float* wq1  = (const float*)d_in[3];
    const float* bq1  = (const float*)d_in[4];
    const float* wq2  = (const float*)d_in[5];
    const float* bq2  = (const float*)d_in[6];
    const float* wq3  = (const float*)d_in[7];
    const float* bq3  = (const float*)d_in[8];
    const float* wq4  = (const float*)d_in[9];
    const float* bq4  = (const float*)d_in[10];
    const float* wk   = (const float*)d_in[11];
    const float* bk   = (const float*)d_in[12];
    const float* wv   = (const float*)d_in[13];
    const float* bv   = (const float*)d_in[14];
    const float* gamma= (const float*)d_in[15];
    float* out = (float*)d_out;

    float *qcat, *q, *k1, *k, *v, *energy, *attnT;
    cudaGetSymbolAddress((void**)&qcat,  g_qcat);
    cudaGetSymbolAddress((void**)&q,     g_q);
    cudaGetSymbolAddress((void**)&k1,    g_k1);
    cudaGetSymbolAddress((void**)&k,     g_k);
    cudaGetSymbolAddress((void**)&v,     g_v);
    cudaGetSymbolAddress((void**)&energy,g_energy);
    cudaGetSymbolAddress((void**)&attnT, g_attnT);

    const dim3 blk(256);
    const dim3 grid64(1, H_, B_);   // COUT=64 convs: TW=64
    const dim3 grid256(2, H_, B_);  // COUT=256 convs: TW=32

    // multi-scale query branch -> qcat (concat via channel offset)
    conv_kernel<64, 1, 1><<<grid64, blk>>>(x, wq,  bq,  qcat, 0,   256);
    conv_kernel<64, 3, 1><<<grid64, blk>>>(x, wq1, bq1, qcat, 64,  256);
    conv_kernel<64, 3, 3><<<grid64, blk>>>(x, wq2, bq2, qcat, 128, 256);
    conv_kernel<64, 3, 6><<<grid64, blk>>>(x, wq3, bq3, qcat, 192, 256);
    // q = 1x1(qcat)
    conv_kernel<256, 1, 1><<<grid256, blk>>>(qcat, wq4, bq4, q, 0, 256);
    // k = conv3x3(conv3x3(x)) with same weights
    conv_kernel<256, 3, 1><<<grid256, blk>>>(x,  wk, bk, k1, 0, 256);
    conv_kernel<256, 3, 1><<<grid256, blk>>>(k1, wk, bk, k,  0, 256);
    // v = 1x1(x)
    conv_kernel<256, 1, 1><<<grid256, blk>>>(x, wv, bv, v, 0, 256);

    // energy[b,i,k,c] = sum_j k[b,i,j,c] * q[b,j,k,c]
    pairmm_kernel<true, false><<<dim3(8,8,8), blk>>>(k, q, energy, nullptr, nullptr);
    // attnT[b,i,j,c] = softmax_c(energy[b,j,i,:])
    softmax_t_kernel<<<NPIXTOT/8, blk>>>(energy, attnT);
    // out[b,i,k,c] = gamma * sum_j attnT[b,i,j,c]*v[b,k,j,c] + x[b,i,k,c]
    pairmm_kernel<false, true><<<dim3(8,8,8), blk>>>(attnT, v, out, x, gamma);
}

// round 8
// speedup vs baseline: 2.8625x; 2.8625x over previous
#include <cuda_runtime.h>
#include <cuda_bf16.h>
#include <cstdint>

#define B_ 8
#define H_ 64
#define W_ 64
#define C_ 256
#define NPIXTOT (B_*H_*W_)

// Scratch (device globals; no allocation allowed)
__device__ float g_qcat[NPIXTOT * C_];
__device__ float g_q[NPIXTOT * C_];
__device__ float g_k1[NPIXTOT * C_];
__device__ float g_k[NPIXTOT * C_];
__device__ float g_v[NPIXTOT * C_];
__device__ float g_energy[NPIXTOT * C_];
__device__ float g_attnT[NPIXTOT * C_];
__device__ uint32_t g_wt[256 * 2304];   // transposed tf32 weights [cout][ktot]

__device__ __forceinline__ uint32_t f2tf32(float f) {
    uint32_t r; asm("cvt.rna.tf32.f32 %0, %1;" : "=r"(r) : "f"(f)); return r;
}

__device__ __forceinline__ void mma_tf32(float* d, const uint32_t* a,
                                         uint32_t b0, uint32_t b1) {
    asm volatile(
        "mma.sync.aligned.m16n8k8.row.col.f32.tf32.tf32.f32 "
        "{%0,%1,%2,%3}, {%4,%5,%6,%7}, {%8,%9}, {%0,%1,%2,%3};"
        : "+f"(d[0]), "+f"(d[1]), "+f"(d[2]), "+f"(d[3])
        : "r"(a[0]), "r"(a[1]), "r"(a[2]), "r"(a[3]), "r"(b0), "r"(b1));
}

// ---------------------------------------------------------------------------
// Weight transpose + tf32 round: wt[cout][tap*256+ci] = tf32(w[tap][ci][cout])
// ---------------------------------------------------------------------------
__global__ __launch_bounds__(256)
void wtrans_kernel(const float* __restrict__ w, uint32_t* __restrict__ wt,
                   int COUT, int KTOT)
{
    int idx = blockIdx.x * 256 + threadIdx.x;
    if (idx >= COUT * KTOT) return;
    int co = idx / KTOT;
    int kk = idx - co * KTOT;
    wt[idx] = f2tf32(w[kk * COUT + co]);
}

// ---------------------------------------------------------------------------
// Implicit-GEMM conv via mma.sync tf32 (m16n8k8).
// BM=128 pixels (2 rows x 64 cols), BN=128/64, BK=32.
// 8 warps in 4x2 grid; warp tile 32 x (BN/2).
// Double-buffered smem (stride 36 floats, conflict-free fragment LDS),
// LDG prefetched one stage ahead.
// ---------------------------------------------------------------------------
template<int COUT, int KS, int DIL>
__global__ __launch_bounds__(256)
void conv_mma_kernel(const float* __restrict__ x, const uint32_t* __restrict__ wt,
                     const float* __restrict__ bias, float* __restrict__ out,
                     int coff, int ctot)
{
    constexpr int KTOT = KS * KS * 256;
    constexpr int NCH  = KS * KS * 8;          // K chunks of 32
    constexpr int BN   = (COUT == 256) ? 128 : 64;
    constexpr int WN   = BN / 2;               // warp n-tile
    constexpr int NA   = WN / 8;               // n8 atoms per warp
    constexpr int AST  = 36;                   // smem row stride (floats)
    constexpr int AL   = 4;                    // A float4 loads / thread / stage
    constexpr int BL   = BN / 32;              // B uint4 loads / thread / stage

    extern __shared__ float sm[];
    float* Asm = sm;                       // [2][128*AST]
    float* Bsm = sm + 2 * 128 * AST;       // [2][BN*AST]

    const int tid  = threadIdx.x;
    const int wid  = tid >> 5;
    const int lane = tid & 31;
    const int wm   = wid >> 1;             // 0..3
    const int wn   = wid & 1;              // 0..1
    const int gr   = lane >> 2;            // 0..7
    const int gc   = lane & 3;             // 0..3

    const int tile = blockIdx.x;
    const int b    = tile >> 5;
    const int h0   = (tile & 31) * 2;
    const int n0   = blockIdx.y * BN;

    float acc[2][NA][4];
    #pragma unroll
    for (int am = 0; am < 2; am++)
        #pragma unroll
        for (int an = 0; an < NA; an++)
            #pragma unroll
            for (int i = 0; i < 4; i++) acc[am][an][i] = 0.f;

    float4 ar[AL];
    uint4  br[BL];

    // --- stage load: gmem -> regs ---
    auto g2r = [&](int ch) {
        const int tap = ch >> 3;
        const int c0  = (ch & 7) * 32;
        const int dy  = (tap / KS - KS / 2) * DIL;
        const int dx  = (tap % KS - KS / 2) * DIL;
        #pragma unroll
        for (int i = 0; i < AL; i++) {
            const int idx = tid + i * 256;
            const int row = idx >> 3;       // pixel row in tile (0..127)
            const int c4  = idx & 7;
            const int ph  = row >> 6;
            const int pw  = row & 63;
            const int h_in = h0 + ph + dy;
            const int w_in = pw + dx;
            float4 v4 = make_float4(0.f, 0.f, 0.f, 0.f);
            if ((unsigned)h_in < 64u && (unsigned)w_in < 64u)
                v4 = *(const float4*)&x[(((b*64 + h_in)*64 + w_in) * 256) + c0 + c4*4];
            ar[i] = v4;
        }
        const int koff = tap * 256 + c0;
        #pragma unroll
        for (int i = 0; i < BL; i++) {
            const int idx = tid + i * 256;
            const int row = idx >> 3;       // cout within tile
            const int c4  = idx & 7;
            br[i] = *(const uint4*)&wt[(n0 + row) * KTOT + koff + c4 * 4];
        }
    };

    // --- stage store: regs -> smem (tf32-round A) ---
    auto r2s = [&](int st) {
        float* As = Asm + st * 128 * AST;
        float* Bs = Bsm + st * BN * AST;
        #pragma unroll
        for (int i = 0; i < AL; i++) {
            const int idx = tid + i * 256;
            const int row = idx >> 3;
            const int c4  = idx & 7;
            uint4 t;
            t.x = f2tf32(ar[i].x); t.y = f2tf32(ar[i].y);
            t.z = f2tf32(ar[i].z); t.w = f2tf32(ar[i].w);
            *(uint4*)&As[row * AST + c4 * 4] = t;
        }
        #pragma unroll
        for (int i = 0; i < BL; i++) {
            const int idx = tid + i * 256;
            const int row = idx >> 3;
            const int c4  = idx & 7;
            *(uint4*)&Bs[row * AST + c4 * 4] = br[i];
        }
    };

    // --- compute one BK=32 stage ---
    auto compute = [&](int st) {
        const float* As = Asm + st * 128 * AST;
        const float* Bs = Bsm + st * BN * AST;
        #pragma unroll
        for (int k8 = 0; k8 < 4; k8++) {
            const int kc = k8 * 8;
            uint32_t afr[2][4];
            #pragma unroll
            for (int am = 0; am < 2; am++) {
                const float* ap = &As[(wm*32 + am*16 + gr) * AST + kc + gc];
                afr[am][0] = __float_as_uint(ap[0]);
                afr[am][1] = __float_as_uint(ap[8 * AST]);
                afr[am][2] = __float_as_uint(ap[4]);
                afr[am][3] = __float_as_uint(ap[8 * AST + 4]);
            }
            #pragma unroll
            for (int an = 0; an < NA; an++) {
                const float* bp = &Bs[(wn*WN + an*8 + gr) * AST + kc + gc];
                const uint32_t b0 = __float_as_uint(bp[0]);
                const uint32_t b1 = __float_as_uint(bp[4]);
                #pragma unroll
                for (int am = 0; am < 2; am++)
                    mma_tf32(acc[am][an], afr[am], b0, b1);
            }
        }
    };

    // --- pipelined mainloop ---
    g2r(0);
    r2s(0);
    if (NCH > 1) g2r(1);
    __syncthreads();
    for (int ch = 0; ch < NCH; ch++) {
        compute(ch & 1);
        if (ch + 1 < NCH) {
            __syncthreads();
            r2s((ch + 1) & 1);
            if (ch + 2 < NCH) g2r(ch + 2);
            __syncthreads();
        }
    }

    // --- epilogue: bias + store ---
    #pragma unroll
    for (int am = 0; am < 2; am++) {
        #pragma unroll
        for (int an = 0; an < NA; an++) {
            const int cl = n0 + wn*WN + an*8 + gc*2;
            const float b0v = bias[cl];
            const float b1v = bias[cl + 1];
            #pragma unroll
            for (int half = 0; half < 2; half++) {
                const int mr = wm*32 + am*16 + gr + half*8;
                const int ph = mr >> 6;
                const int pw = mr & 63;
                float2 o;
                o.x = acc[am][an][half*2 + 0] + b0v;
                o.y = acc[am][an][half*2 + 1] + b1v;
                *(float2*)&out[(((b*64 + h0 + ph)*64 + pw) * ctot) + coff + cl] = o;
            }
        }
    }
}

// ---------------------------------------------------------------------------
// Per-channel spatial "matmul": acc[i,k,c] = sum_j A[b,i,j,c] * Brow(j,k)[c]
// ---------------------------------------------------------------------------
template<bool SWAPB, bool FUSE>
__global__ __launch_bounds__(256)
void pairmm_kernel(const float* __restrict__ A, const float* __restrict__ Bm,
                   float* __restrict__ out, const float* __restrict__ x,
                   const float* __restrict__ gammap)
{
    __shared__ float As[8 * 256];
    __shared__ float Bs[8 * 256];

    const int c  = threadIdx.x;
    const int i0 = blockIdx.x * 8;
    const int k0 = blockIdx.y * 8;
    const int b  = blockIdx.z;

    float acc[8][8];
    #pragma unroll
    for (int ii = 0; ii < 8; ii++)
        #pragma unroll
        for (int kk = 0; kk < 8; kk++) acc[ii][kk] = 0.f;

    for (int j = 0; j < 64; j++) {
        #pragma unroll
        for (int r = 0; r < 8; r++) {
            As[r*256 + c] = A[(((b*64 + i0 + r)*64 + j) * 256) + c];
            const int brow = SWAPB ? ((b*64 + j)*64 + (k0 + r))
                                   : ((b*64 + (k0 + r))*64 + j);
            Bs[r*256 + c] = Bm[brow * 256 + c];
        }
        __syncthreads();
        float bv[8];
        #pragma unroll
        for (int kk = 0; kk < 8; kk++) bv[kk] = Bs[kk*256 + c];
        #pragma unroll
        for (int ii = 0; ii < 8; ii++) {
            const float av = As[ii*256 + c];
            #pragma unroll
            for (int kk = 0; kk < 8; kk++)
                acc[ii][kk] = fmaf(av, bv[kk], acc[ii][kk]);
        }
        __syncthreads();
    }

    const float gm = FUSE ? gammap[0] : 0.f;
    #pragma unroll
    for (int ii = 0; ii < 8; ii++) {
        #pragma unroll
        for (int kk = 0; kk < 8; kk++) {
            const int idx = (((b*64 + i0 + ii)*64 + (k0 + kk)) * 256) + c;
            if (FUSE) out[idx] = gm * acc[ii][kk] + x[idx];
            else      out[idx] = acc[ii][kk];
        }
    }
}

// ---------------------------------------------------------------------------
// Softmax over channels with transposed spatial write
// ---------------------------------------------------------------------------
__global__ __launch_bounds__(256)
void softmax_t_kernel(const float* __restrict__ e, float* __restrict__ at)
{
    const int warp = threadIdx.x / 32;
    const int lane = threadIdx.x % 32;
    const int row  = blockIdx.x * 8 + warp;

    const float* er = &e[row * 256];
    float v[8];
    float m = -1e30f;
    #pragma unroll
    for (int s = 0; s < 8; s++) { v[s] = er[lane + 32*s]; m = fmaxf(m, v[s]); }
    #pragma unroll
    for (int o = 16; o; o >>= 1) m = fmaxf(m, __shfl_xor_sync(0xffffffffu, m, o));
    float sum = 0.f;
    #pragma unroll
    for (int s = 0; s < 8; s++) { v[s] = __expf(v[s] - m); sum += v[s]; }
    #pragma unroll
    for (int o = 16; o; o >>= 1) sum += __shfl_xor_sync(0xffffffffu, sum, o);
    const float inv = 1.0f / sum;

    const int ii  = row % 64;
    const int bjj = row / 64;
    const int jj  = bjj % 64;
    const int b   = bjj / 64;
    float* orow = &at[((b*64 + ii)*64 + jj) * 256];
    #pragma unroll
    for (int s = 0; s < 8; s++) orow[lane + 32*s] = v[s] * inv;
}

// ---------------------------------------------------------------------------
extern "C" void kernel_launch(void* const* d_in, const int* in_sizes, int n_in,
                              void* d_out, int out_size)
{
    const float* x    = (const float*)d_in[0];
    const float* wq   = (const float*)d_in[1];
    const float* bq   = (const float*)d_in[2];
    const float* wq1  = (const float*)d_in[3];
    const float* bq1  = (const float*)d_in[4];
    const float* wq2  = (const float*)d_in[5];
    const float* bq2  = (const float*)d_in[6];
    const float* wq3  = (const float*)d_in[7];
    const float* bq3  = (const float*)d_in[8];
    const float* wq4  = (const float*)d_in[9];
    const float* bq4  = (const float*)d_in[10];
    const float* wk   = (const float*)d_in[11];
    const float* bk   = (const float*)d_in[12];
    const float* wv   = (const float*)d_in[13];
    const float* bv   = (const float*)d_in[14];
    const float* gamma= (const float*)d_in[15];
    float* out = (float*)d_out;

    float *qcat, *q, *k1, *k, *v, *energy, *attnT; uint32_t* wt;
    cudaGetSymbolAddress((void**)&qcat,  g_qcat);
    cudaGetSymbolAddress((void**)&q,     g_q);
    cudaGetSymbolAddress((void**)&k1,    g_k1);
    cudaGetSymbolAddress((void**)&k,     g_k);
    cudaGetSymbolAddress((void**)&v,     g_v);
    cudaGetSymbolAddress((void**)&energy,g_energy);
    cudaGetSymbolAddress((void**)&attnT, g_attnT);
    cudaGetSymbolAddress((void**)&wt,    g_wt);

    // dynamic smem: (2*128 + 2*BN) * 36 floats
    const int SM256 = (2*128 + 2*128) * 36 * 4;   // 73728
    const int SM64  = (2*128 + 2*64)  * 36 * 4;   // 55296
    cudaFuncSetAttribute(conv_mma_kernel<256,3,1>, cudaFuncAttributeMaxDynamicSharedMemorySize, SM256);
    cudaFuncSetAttribute(conv_mma_kernel<256,1,1>, cudaFuncAttributeMaxDynamicSharedMemorySize, SM256);
    cudaFuncSetAttribute(conv_mma_kernel<64,1,1>,  cudaFuncAttributeMaxDynamicSharedMemorySize, SM64);
    cudaFuncSetAttribute(conv_mma_kernel<64,3,1>,  cudaFuncAttributeMaxDynamicSharedMemorySize, SM64);
    cudaFuncSetAttribute(conv_mma_kernel<64,3,3>,  cudaFuncAttributeMaxDynamicSharedMemorySize, SM64);
    cudaFuncSetAttribute(conv_mma_kernel<64,3,6>,  cudaFuncAttributeMaxDynamicSharedMemorySize, SM64);

    const dim3 cblk(256);
    const dim3 g256(256, 2);   // COUT=256: 2 N-tiles of 128
    const dim3 g64(256, 1);    // COUT=64

    // k-branch: transpose wk once, apply twice (same weights)
    wtrans_kernel<<<(256*2304 + 255)/256, 256>>>(wk, wt, 256, 2304);
    conv_mma_kernel<256,3,1><<<g256, cblk, SM256>>>(x,  wt, bk, k1, 0, 256);
    conv_mma_kernel<256,3,1><<<g256, cblk, SM256>>>(k1, wt, bk, k,  0, 256);
    // multi-scale query branch -> qcat
    wtrans_kernel<<<(64*256 + 255)/256, 256>>>(wq, wt, 64, 256);
    conv_mma_kernel<64,1,1><<<g64, cblk, SM64>>>(x, wt, bq,  qcat, 0,   256);
    wtrans_kernel<<<(64*2304 + 255)/256, 256>>>(wq1, wt, 64, 2304);
    conv_mma_kernel<64,3,1><<<g64, cblk, SM64>>>(x, wt, bq1, qcat, 64,  256);
    wtrans_kernel<<<(64*2304 + 255)/256, 256>>>(wq2, wt, 64, 2304);
    conv_mma_kernel<64,3,3><<<g64, cblk, SM64>>>(x, wt, bq2, qcat, 128, 256);
    wtrans_kernel<<<(64*2304 + 255)/256, 256>>>(wq3, wt, 64, 2304);
    conv_mma_kernel<64,3,6><<<g64, cblk, SM64>>>(x, wt, bq3, qcat, 192, 256);
    // q = 1x1(qcat)
    wtrans_kernel<<<(256*256 + 255)/256, 256>>>(wq4, wt, 256, 256);
    conv_mma_kernel<256,1,1><<<g256, cblk, SM256>>>(qcat, wt, bq4, q, 0, 256);
    // v = 1x1(x)
    wtrans_kernel<<<(256*256 + 255)/256, 256>>>(wv, wt, 256, 256);
    conv_mma_kernel<256,1,1><<<g256, cblk, SM256>>>(x, wt, bv, v, 0, 256);

    // attention
    pairmm_kernel<true, false><<<dim3(8,8,8), dim3(256)>>>(k, q, energy, nullptr, nullptr);
    softmax_t_kernel<<<NPIXTOT/8, dim3(256)>>>(energy, attnT);
    pairmm_kernel<false, true><<<dim3(8,8,8), dim3(256)>>>(attnT, v, out, x, gamma);
}

// round 9
// speedup vs baseline: 3.3910x; 1.1847x over previous
#include <cuda_runtime.h>
#include <cuda_bf16.h>
#include <cstdint>

#define B_ 8
#define H_ 64
#define W_ 64
#define C_ 256
#define NPIXTOT (B_*H_*W_)

// Scratch (device globals; no allocation allowed)
__device__ float g_qcat[NPIXTOT * C_];
__device__ float g_q[NPIXTOT * C_];
__device__ float g_k1[NPIXTOT * C_];
__device__ float g_k[NPIXTOT * C_];
__device__ float g_v[NPIXTOT * C_];
__device__ float g_energy[NPIXTOT * C_];
__device__ float g_attnT[NPIXTOT * C_];
// transposed tf32 weights, all convs resident simultaneously
// wk:0 (589824) | wq4:589824 (65536) | wv:655360 (65536)
// wq1:720896 | wq2:868352 | wq3:1015808 (147456 each) | wq:1163264 (16384)
__device__ uint32_t g_wt[1179648];

#define WT_WK   0
#define WT_WQ4  589824
#define WT_WV   655360
#define WT_WQ1  720896
#define WT_WQ2  868352
#define WT_WQ3  1015808
#define WT_WQ   1163264

__device__ __forceinline__ uint32_t f2tf32(float f) {
    uint32_t r; asm("cvt.rna.tf32.f32 %0, %1;" : "=r"(r) : "f"(f)); return r;
}

__device__ __forceinline__ void mma_tf32(float* d, const uint32_t* a,
                                         uint32_t b0, uint32_t b1) {
    asm volatile(
        "mma.sync.aligned.m16n8k8.row.col.f32.tf32.tf32.f32 "
        "{%0,%1,%2,%3}, {%4,%5,%6,%7}, {%8,%9}, {%0,%1,%2,%3};"
        : "+f"(d[0]), "+f"(d[1]), "+f"(d[2]), "+f"(d[3])
        : "r"(a[0]), "r"(a[1]), "r"(a[2]), "r"(a[3]), "r"(b0), "r"(b1));
}

__device__ __forceinline__ void cp16(uint32_t saddr, const void* gaddr, uint32_t sz) {
    asm volatile("cp.async.ca.shared.global [%0], [%1], 16, %2;"
                 :: "r"(saddr), "l"(gaddr), "r"(sz) : "memory");
}
__device__ __forceinline__ void cp_commit() {
    asm volatile("cp.async.commit_group;" ::: "memory");
}
__device__ __forceinline__ void cp_wait1() {
    asm volatile("cp.async.wait_group 1;" ::: "memory");
}

// ---------------------------------------------------------------------------
// Weight transpose + tf32 round: wt[cout][tap*256+ci] = tf32(w[tap][ci][cout])
// ---------------------------------------------------------------------------
__global__ __launch_bounds__(256)
void wtrans_kernel(const float* __restrict__ w, uint32_t* __restrict__ wt,
                   int COUT, int KTOT)
{
    int idx = blockIdx.x * 256 + threadIdx.x;
    if (idx >= COUT * KTOT) return;
    int co = idx / KTOT;
    int kk = idx - co * KTOT;
    wt[idx] = f2tf32(w[kk * COUT + co]);
}

// ---------------------------------------------------------------------------
// Implicit-GEMM conv via mma.sync tf32 (m16n8k8), cp.async 3-stage pipeline.
// BM=128 pixels (2 rows x 64 cols), BN=128/64, BK=32.
// 8 warps in 4x2 grid; warp tile 32 x (BN/2). smem stride 36 (conflict-free).
// ---------------------------------------------------------------------------
template<int COUT, int KS>
__device__ __forceinline__
void conv_body(const float* __restrict__ x, const uint32_t* __restrict__ wt,
               const float* __restrict__ bias, float* __restrict__ out,
               int coff, int ctot, int dil, int tile, int n0)
{
    constexpr int KTOT   = KS * KS * 256;
    constexpr int NCH    = KS * KS * 8;          // K chunks of 32
    constexpr int BN     = (COUT == 256) ? 128 : 64;
    constexpr int WN     = BN / 2;
    constexpr int NA     = WN / 8;
    constexpr int AST    = 36;
    constexpr int AL     = 4;                    // A 16B copies / thread / stage
    constexpr int BL     = BN / 32;              // B 16B copies / thread / stage
    constexpr int STAGES = 3;

    extern __shared__ float sm[];
    float* Asm = sm;                             // [STAGES][128*AST]
    float* Bsm = sm + STAGES * 128 * AST;        // [STAGES][BN*AST]

    const int tid  = threadIdx.x;
    const int wid  = tid >> 5;
    const int lane = tid & 31;
    const int wm   = wid >> 1;
    const int wn   = wid & 1;
    const int gr   = lane >> 2;
    const int gc   = lane & 3;

    const int b  = tile >> 5;
    const int h0 = (tile & 31) * 2;

    float acc[2][NA][4];
    #pragma unroll
    for (int am = 0; am < 2; am++)
        #pragma unroll
        for (int an = 0; an < NA; an++)
            #pragma unroll
            for (int i = 0; i < 4; i++) acc[am][an][i] = 0.f;

    auto issue = [&](int ch) {
        const int st  = ch % STAGES;
        const int tap = ch >> 3;
        const int c0  = (ch & 7) * 32;
        const int dy  = (tap / KS - KS / 2) * dil;
        const int dx  = (tap % KS - KS / 2) * dil;
        float* As = Asm + st * 128 * AST;
        float* Bs = Bsm + st * BN * AST;
        #pragma unroll
        for (int i = 0; i < AL; i++) {
            const int idx = tid + i * 256;
            const int row = idx >> 3;
            const int c4  = idx & 7;
            const int ph  = row >> 6;
            const int pw  = row & 63;
            const int h_in = h0 + ph + dy;
            const int w_in = pw + dx;
            const bool valid = ((unsigned)h_in < 64u) && ((unsigned)w_in < 64u);
            const float* src = valid
                ? &x[(((b*64 + h_in)*64 + w_in) * 256) + c0 + c4*4] : x;
            cp16((uint32_t)__cvta_generic_to_shared(&As[row * AST + c4 * 4]),
                 src, valid ? 16u : 0u);
        }
        const int koff = tap * 256 + c0;
        #pragma unroll
        for (int i = 0; i < BL; i++) {
            const int idx = tid + i * 256;
            const int row = idx >> 3;
            const int c4  = idx & 7;
            cp16((uint32_t)__cvta_generic_to_shared(&Bs[row * AST + c4 * 4]),
                 &wt[(n0 + row) * KTOT + koff + c4 * 4], 16u);
        }
        cp_commit();
    };

    auto compute = [&](int st) {
        const float* As = Asm + st * 128 * AST;
        const float* Bs = Bsm + st * BN * AST;
        #pragma unroll
        for (int k8 = 0; k8 < 4; k8++) {
            const int kc = k8 * 8;
            uint32_t afr[2][4];
            #pragma unroll
            for (int am = 0; am < 2; am++) {
                const float* ap = &As[(wm*32 + am*16 + gr) * AST + kc + gc];
                afr[am][0] = __float_as_uint(ap[0]);
                afr[am][1] = __float_as_uint(ap[8 * AST]);
                afr[am][2] = __float_as_uint(ap[4]);
                afr[am][3] = __float_as_uint(ap[8 * AST + 4]);
            }
            #pragma unroll
            for (int an = 0; an < NA; an++) {
                const float* bp = &Bs[(wn*WN + an*8 + gr) * AST + kc + gc];
                const uint32_t b0 = __float_as_uint(bp[0]);
                const uint32_t b1 = __float_as_uint(bp[4]);
                #pragma unroll
                for (int am = 0; am < 2; am++)
                    mma_tf32(acc[am][an], afr[am], b0, b1);
            }
        }
    };

    // prologue: STAGES-1 groups in flight
    issue(0);
    issue(1);
    for (int ch = 0; ch < NCH; ch++) {
        cp_wait1();            // with one commit/iter, guarantees group ch done
        __syncthreads();
        if (ch + 2 < NCH) issue(ch + 2);
        else              cp_commit();   // empty group keeps numbering
        compute(ch % STAGES);
        __syncthreads();
    }

    // epilogue: bias + store
    #pragma unroll
    for (int am = 0; am < 2; am++) {
        #pragma unroll
        for (int an = 0; an < NA; an++) {
            const int cl = n0 + wn*WN + an*8 + gc*2;
            const float b0v = bias[cl];
            const float b1v = bias[cl + 1];
            #pragma unroll
            for (int half = 0; half < 2; half++) {
                const int mr = wm*32 + am*16 + gr + half*8;
                const int ph = mr >> 6;
                const int pw = mr & 63;
                float2 o;
                o.x = acc[am][an][half*2 + 0] + b0v;
                o.y = acc[am][an][half*2 + 1] + b1v;
                *(float2*)&out[(((b*64 + h0 + ph)*64 + pw) * ctot) + coff + cl] = o;
            }
        }
    }
}

template<int COUT, int KS>
__global__ __launch_bounds__(256)
void conv_g(const float* __restrict__ x, const uint32_t* __restrict__ wt,
            const float* __restrict__ bias, float* __restrict__ out,
            int coff, int ctot, int dil)
{
    constexpr int BN = (COUT == 256) ? 128 : 64;
    conv_body<COUT, KS>(x, wt, bias, out, coff, ctot, dil,
                        blockIdx.x, blockIdx.y * BN);
}

// Fused 3-dilation query conv: blockIdx.z selects branch (dil 1/3/6)
__global__ __launch_bounds__(256)
void qconv3_g(const float* __restrict__ x, const uint32_t* __restrict__ wt,
              const float* __restrict__ b1, const float* __restrict__ b2,
              const float* __restrict__ b3, float* __restrict__ out)
{
    const int z = blockIdx.z;
    const int dil = (z == 0) ? 1 : ((z == 1) ? 3 : 6);
    const float* bias = (z == 0) ? b1 : ((z == 1) ? b2 : b3);
    conv_body<64, 3>(x, wt + z * 64 * 2304, bias, out,
                     64 + z * 64, 256, dil, blockIdx.x, 0);
}

// ---------------------------------------------------------------------------
// Per-channel spatial "matmul", double-buffered (1 sync / j, prefetch j+1):
// acc[i,k,c] = sum_j A[b,i,j,c] * Brow(j,k)[c]
// ---------------------------------------------------------------------------
template<bool SWAPB, bool FUSE>
__global__ __launch_bounds__(256)
void pairmm_kernel(const float* __restrict__ A, const float* __restrict__ Bm,
                   float* __restrict__ out, const float* __restrict__ x,
                   const float* __restrict__ gammap)
{
    __shared__ float As[2][8 * 256];
    __shared__ float Bs[2][8 * 256];

    const int c  = threadIdx.x;
    const int i0 = blockIdx.x * 8;
    const int k0 = blockIdx.y * 8;
    const int b  = blockIdx.z;

    float acc[8][8];
    #pragma unroll
    for (int ii = 0; ii < 8; ii++)
        #pragma unroll
        for (int kk = 0; kk < 8; kk++) acc[ii][kk] = 0.f;

    float ar[8], brg[8];
    auto load = [&](int j) {
        #pragma unroll
        for (int r = 0; r < 8; r++) {
            ar[r] = A[(((b*64 + i0 + r)*64 + j) * 256) + c];
            const int brow = SWAPB ? ((b*64 + j)*64 + (k0 + r))
                                   : ((b*64 + (k0 + r))*64 + j);
            brg[r] = Bm[brow * 256 + c];
        }
    };

    load(0);
    for (int j = 0; j < 64; j++) {
        const int st = j & 1;
        #pragma unroll
        for (int r = 0; r < 8; r++) {
            As[st][r*256 + c] = ar[r];
            Bs[st][r*256 + c] = brg[r];
        }
        __syncthreads();
        if (j + 1 < 64) load(j + 1);
        float bv[8];
        #pragma unroll
        for (int kk = 0; kk < 8; kk++) bv[kk] = Bs[st][kk*256 + c];
        #pragma unroll
        for (int ii = 0; ii < 8; ii++) {
            const float av = As[st][ii*256 + c];
            #pragma unroll
            for (int kk = 0; kk < 8; kk++)
                acc[ii][kk] = fmaf(av, bv[kk], acc[ii][kk]);
        }
    }

    const float gm = FUSE ? gammap[0] : 0.f;
    #pragma unroll
    for (int ii = 0; ii < 8; ii++) {
        #pragma unroll
        for (int kk = 0; kk < 8; kk++) {
            const int idx = (((b*64 + i0 + ii)*64 + (k0 + kk)) * 256) + c;
            if (FUSE) out[idx] = gm * acc[ii][kk] + x[idx];
            else      out[idx] = acc[ii][kk];
        }
    }
}

// ---------------------------------------------------------------------------
// Softmax over channels with transposed spatial write
// ---------------------------------------------------------------------------
__global__ __launch_bounds__(256)
void softmax_t_kernel(const float* __restrict__ e, float* __restrict__ at)
{
    const int warp = threadIdx.x / 32;
    const int lane = threadIdx.x % 32;
    const int row  = blockIdx.x * 8 + warp;

    const float* er = &e[row * 256];
    float v[8];
    float m = -1e30f;
    #pragma unroll
    for (int s = 0; s < 8; s++) { v[s] = er[lane + 32*s]; m = fmaxf(m, v[s]); }
    #pragma unroll
    for (int o = 16; o; o >>= 1) m = fmaxf(m, __shfl_xor_sync(0xffffffffu, m, o));
    float sum = 0.f;
    #pragma unroll
    for (int s = 0; s < 8; s++) { v[s] = __expf(v[s] - m); sum += v[s]; }
    #pragma unroll
    for (int o = 16; o; o >>= 1) sum += __shfl_xor_sync(0xffffffffu, sum, o);
    const float inv = 1.0f / sum;

    const int ii  = row % 64;
    const int bjj = row / 64;
    const int jj  = bjj % 64;
    const int b   = bjj / 64;
    float* orow = &at[((b*64 + ii)*64 + jj) * 256];
    #pragma unroll
    for (int s = 0; s < 8; s++) orow[lane + 32*s] = v[s] * inv;
}

// ---------------------------------------------------------------------------
extern "C" void kernel_launch(void* const* d_in, const int* in_sizes, int n_in,
                              void* d_out, int out_size)
{
    const float* x    = (const float*)d_in[0];
    const float* wq   = (const float*)d_in[1];
    const float* bq   = (const float*)d_in[2];
    const float* wq1  = (const float*)d_in[3];
    const float* bq1  = (const float*)d_in[4];
    const float* wq2  = (const float*)d_in[5];
    const float* bq2  = (const float*)d_in[6];
    const float* wq3  = (const float*)d_in[7];
    const float* bq3  = (const float*)d_in[8];
    const float* wq4  = (const float*)d_in[9];
    const float* bq4  = (const float*)d_in[10];
    const float* wk   = (const float*)d_in[11];
    const float* bk   = (const float*)d_in[12];
    const float* wv   = (const float*)d_in[13];
    const float* bv   = (const float*)d_in[14];
    const float* gamma= (const float*)d_in[15];
    float* out = (float*)d_out;

    float *qcat, *q, *k1, *k, *v, *energy, *attnT; uint32_t* wt;
    cudaGetSymbolAddress((void**)&qcat,  g_qcat);
    cudaGetSymbolAddress((void**)&q,     g_q);
    cudaGetSymbolAddress((void**)&k1,    g_k1);
    cudaGetSymbolAddress((void**)&k,     g_k);
    cudaGetSymbolAddress((void**)&v,     g_v);
    cudaGetSymbolAddress((void**)&energy,g_energy);
    cudaGetSymbolAddress((void**)&attnT, g_attnT);
    cudaGetSymbolAddress((void**)&wt,    g_wt);

    // dynamic smem: 3 stages * (128 + BN) * 36 floats
    const int SM256 = 3 * (128 + 128) * 36 * 4;   // 110592
    const int SM64  = 3 * (128 + 64)  * 36 * 4;   // 82944
    cudaFuncSetAttribute(conv_g<256,3>, cudaFuncAttributeMaxDynamicSharedMemorySize, SM256);
    cudaFuncSetAttribute(conv_g<256,1>, cudaFuncAttributeMaxDynamicSharedMemorySize, SM256);
    cudaFuncSetAttribute(conv_g<64,1>,  cudaFuncAttributeMaxDynamicSharedMemorySize, SM64);
    cudaFuncSetAttribute(qconv3_g,      cudaFuncAttributeMaxDynamicSharedMemorySize, SM64);

    const dim3 cblk(256);

    // --- all weight transposes up front (independent slabs) ---
    wtrans_kernel<<<(256*2304 + 255)/256, 256>>>(wk,  wt + WT_WK,  256, 2304);
    wtrans_kernel<<<(256*256  + 255)/256, 256>>>(wq4, wt + WT_WQ4, 256, 256);
    wtrans_kernel<<<(256*256  + 255)/256, 256>>>(wv,  wt + WT_WV,  256, 256);
    wtrans_kernel<<<(64*2304  + 255)/256, 256>>>(wq1, wt + WT_WQ1, 64, 2304);
    wtrans_kernel<<<(64*2304  + 255)/256, 256>>>(wq2, wt + WT_WQ2, 64, 2304);
    wtrans_kernel<<<(64*2304  + 255)/256, 256>>>(wq3, wt + WT_WQ3, 64, 2304);
    wtrans_kernel<<<(64*256   + 255)/256, 256>>>(wq,  wt + WT_WQ,  64, 256);

    // k = conv3x3(conv3x3(x)), same weights
    conv_g<256,3><<<dim3(256,2), cblk, SM256>>>(x,  wt + WT_WK, bk, k1, 0, 256, 1);
    conv_g<256,3><<<dim3(256,2), cblk, SM256>>>(k1, wt + WT_WK, bk, k,  0, 256, 1);
    // query branch -> qcat: 1x1 + fused 3-dilation 3x3
    conv_g<64,1><<<dim3(256,1), cblk, SM64>>>(x, wt + WT_WQ, bq, qcat, 0, 256, 1);
    qconv3_g<<<dim3(256,1,3), cblk, SM64>>>(x, wt + WT_WQ1, bq1, bq2, bq3, qcat);
    // q = 1x1(qcat), v = 1x1(x)
    conv_g<256,1><<<dim3(256,2), cblk, SM256>>>(qcat, wt + WT_WQ4, bq4, q, 0, 256, 1);
    conv_g<256,1><<<dim3(256,2), cblk, SM256>>>(x,    wt + WT_WV,  bv,  v, 0, 256, 1);

    // attention
    pairmm_kernel<true, false><<<dim3(8,8,8), dim3(256)>>>(k, q, energy, nullptr, nullptr);
    softmax_t_kernel<<<NPIXTOT/8, dim3(256)>>>(energy, attnT);
    pairmm_kernel<false, true><<<dim3(8,8,8), dim3(256)>>>(attnT, v, out, x, gamma);
}

// round 10
// speedup vs baseline: 4.8694x; 1.4360x over previous
#include <cuda_runtime.h>
#include <cuda_fp16.h>
#include <cstdint>

#define B_ 8
#define H_ 64
#define W_ 64
#define C_ 256
#define NPIXTOT (B_*H_*W_)

// Scratch (device globals; no allocation allowed)
__device__ __half g_xh[NPIXTOT * C_];     // fp16 input
__device__ __half g_k1h[NPIXTOT * C_];    // fp16 intermediate (k branch)
__device__ __half g_qcath[NPIXTOT * C_];  // fp16 concat (q branch)
__device__ float  g_q[NPIXTOT * C_];
__device__ float  g_k[NPIXTOT * C_];
__device__ float  g_v[NPIXTOT * C_];
__device__ float  g_energy[NPIXTOT * C_];
__device__ float  g_attnT[NPIXTOT * C_];
// transposed fp16 weights [cout][ktot]
// wk:0 (589824) | wq4:589824 (65536) | wv:655360 (65536)
// wq1:720896 | wq2:868352 | wq3:1015808 (147456 each) | wq:1163264 (16384)
__device__ __half g_wt[1179648];

#define WT_WK   0
#define WT_WQ4  589824
#define WT_WV   655360
#define WT_WQ1  720896
#define WT_WQ2  868352
#define WT_WQ3  1015808
#define WT_WQ   1163264

__device__ __forceinline__ void mma_f16(float* d, const uint32_t* a,
                                        uint32_t b0, uint32_t b1) {
    asm volatile(
        "mma.sync.aligned.m16n8k16.row.col.f32.f16.f16.f32 "
        "{%0,%1,%2,%3}, {%4,%5,%6,%7}, {%8,%9}, {%0,%1,%2,%3};"
        : "+f"(d[0]), "+f"(d[1]), "+f"(d[2]), "+f"(d[3])
        : "r"(a[0]), "r"(a[1]), "r"(a[2]), "r"(a[3]), "r"(b0), "r"(b1));
}

__device__ __forceinline__ void cp16(uint32_t saddr, const void* gaddr, uint32_t sz) {
    asm volatile("cp.async.ca.shared.global [%0], [%1], 16, %2;"
                 :: "r"(saddr), "l"(gaddr), "r"(sz) : "memory");
}
__device__ __forceinline__ void cp_commit() {
    asm volatile("cp.async.commit_group;" ::: "memory");
}
__device__ __forceinline__ void cp_wait1() {
    asm volatile("cp.async.wait_group 1;" ::: "memory");
}

// ---------------------------------------------------------------------------
// x -> fp16 pre-pass (float4 -> half2x2)
// ---------------------------------------------------------------------------
__global__ __launch_bounds__(256)
void x2h_kernel(const float* __restrict__ x, __half* __restrict__ xh)
{
    const int i4 = blockIdx.x * 256 + threadIdx.x;   // float4 index
    const float4 v = *(const float4*)&x[i4 * 4];
    __half2* o = (__half2*)&xh[i4 * 4];
    o[0] = __floats2half2_rn(v.x, v.y);
    o[1] = __floats2half2_rn(v.z, v.w);
}

// ---------------------------------------------------------------------------
// Weight transpose + fp16 round: wt[cout][tap*256+ci] = h(w[tap][ci][cout])
// ---------------------------------------------------------------------------
__global__ __launch_bounds__(256)
void wtrans_kernel(const float* __restrict__ w, __half* __restrict__ wt,
                   int COUT, int KTOT)
{
    int idx = blockIdx.x * 256 + threadIdx.x;
    if (idx >= COUT * KTOT) return;
    int co = idx / KTOT;
    int kk = idx - co * KTOT;
    wt[idx] = __float2half_rn(w[kk * COUT + co]);
}

// ---------------------------------------------------------------------------
// Implicit-GEMM conv via mma.sync fp16 (m16n8k16), cp.async 3-stage pipeline.
// BM=128 pixels (2 rows x 64 cols), BN=128/64, BK=32 channels (2 k16 steps).
// 8 warps (4x2); warp tile 32 x (BN/2). smem b32-pair rows, stride 20 words.
// OUTH: write fp16 output (feeds another conv) vs fp32 (feeds attention).
// ---------------------------------------------------------------------------
template<int COUT, int KS, bool OUTH>
__device__ __forceinline__
void conv_body(const __half* __restrict__ x, const __half* __restrict__ wt,
               const float* __restrict__ bias, void* __restrict__ outp,
               int coff, int ctot, int dil, int tile, int n0)
{
    constexpr int KTOT   = KS * KS * 256;
    constexpr int NCH    = KS * KS * 8;          // chunks of 32 channels
    constexpr int BN     = (COUT == 256) ? 128 : 64;
    constexpr int WN     = BN / 2;
    constexpr int NA     = WN / 8;
    constexpr int AST    = 20;                   // b32 words per row (16+4 pad)
    constexpr int AL     = 2;                    // A 16B copies / thread / stage
    constexpr int BL     = BN / 64;              // B 16B copies / thread / stage
    constexpr int STAGES = 3;

    extern __shared__ uint32_t sm32[];
    uint32_t* Asm = sm32;                        // [STAGES][128*AST]
    uint32_t* Bsm = sm32 + STAGES * 128 * AST;   // [STAGES][BN*AST]

    const int tid  = threadIdx.x;
    const int wid  = tid >> 5;
    const int lane = tid & 31;
    const int wm   = wid >> 1;
    const int wn   = wid & 1;
    const int gr   = lane >> 2;
    const int gc   = lane & 3;

    const int b  = tile >> 5;
    const int h0 = (tile & 31) * 2;

    float acc[2][NA][4];
    #pragma unroll
    for (int am = 0; am < 2; am++)
        #pragma unroll
        for (int an = 0; an < NA; an++)
            #pragma unroll
            for (int i = 0; i < 4; i++) acc[am][an][i] = 0.f;

    auto issue = [&](int ch) {
        const int st  = ch % STAGES;
        const int tap = ch >> 3;
        const int c0  = (ch & 7) * 32;
        const int dy  = (tap / KS - KS / 2) * dil;
        const int dx  = (tap % KS - KS / 2) * dil;
        uint32_t* As = Asm + st * 128 * AST;
        uint32_t* Bs = Bsm + st * BN * AST;
        // A: 128 rows x 4 chunks of 16B (8 halves each)
        #pragma unroll
        for (int i = 0; i < AL; i++) {
            const int idx = tid + i * 256;
            const int row = idx >> 2;
            const int c16 = idx & 3;
            const int ph  = row >> 6;
            const int pw  = row & 63;
            const int h_in = h0 + ph + dy;
            const int w_in = pw + dx;
            const bool valid = ((unsigned)h_in < 64u) && ((unsigned)w_in < 64u);
            const __half* src = valid
                ? &x[(((b*64 + h_in)*64 + w_in) * 256) + c0 + c16*8] : x;
            cp16((uint32_t)__cvta_generic_to_shared(&As[row * AST + c16 * 4]),
                 src, valid ? 16u : 0u);
        }
        const int koff = tap * 256 + c0;
        #pragma unroll
        for (int i = 0; i < BL; i++) {
            const int idx = tid + i * 256;
            const int row = idx >> 2;
            const int c16 = idx & 3;
            cp16((uint32_t)__cvta_generic_to_shared(&Bs[row * AST + c16 * 4]),
                 &wt[(n0 + row) * KTOT + koff + c16 * 8], 16u);
        }
        cp_commit();
    };

    auto compute = [&](int st) {
        const uint32_t* As = Asm + st * 128 * AST;
        const uint32_t* Bs = Bsm + st * BN * AST;
        #pragma unroll
        for (int s = 0; s < 2; s++) {          // two k16 steps per 32-ch stage
            const int kp = s * 8;              // pair offset
            uint32_t afr[2][4];
            #pragma unroll
            for (int am = 0; am < 2; am++) {
                const uint32_t* ap = &As[(wm*32 + am*16 + gr) * AST + kp + gc];
                afr[am][0] = ap[0];
                afr[am][1] = ap[8 * AST];
                afr[am][2] = ap[4];
                afr[am][3] = ap[8 * AST + 4];
            }
            #pragma unroll
            for (int an = 0; an < NA; an++) {
                const uint32_t* bp = &Bs[(wn*WN + an*8 + gr) * AST + kp + gc];
                const uint32_t b0 = bp[0];
                const uint32_t b1 = bp[4];
                #pragma unroll
                for (int am = 0; am < 2; am++)
                    mma_f16(acc[am][an], afr[am], b0, b1);
            }
        }
    };

    issue(0);
    issue(1);
    for (int ch = 0; ch < NCH; ch++) {
        cp_wait1();
        __syncthreads();
        if (ch + 2 < NCH) issue(ch + 2);
        else              cp_commit();
        compute(ch % STAGES);
        __syncthreads();
    }

    // epilogue: bias + store (fp32 or fp16)
    #pragma unroll
    for (int am = 0; am < 2; am++) {
        #pragma unroll
        for (int an = 0; an < NA; an++) {
            const int cl = n0 + wn*WN + an*8 + gc*2;
            const float b0v = bias[cl];
            const float b1v = bias[cl + 1];
            #pragma unroll
            for (int half = 0; half < 2; half++) {
                const int mr = wm*32 + am*16 + gr + half*8;
                const int ph = mr >> 6;
                const int pw = mr & 63;
                const int base = (((b*64 + h0 + ph)*64 + pw) * ctot) + coff + cl;
                const float o0 = acc[am][an][half*2 + 0] + b0v;
                const float o1 = acc[am][an][half*2 + 1] + b1v;
                if (OUTH) {
                    *(__half2*)&((__half*)outp)[base] = __floats2half2_rn(o0, o1);
                } else {
                    *(float2*)&((float*)outp)[base] = make_float2(o0, o1);
                }
            }
        }
    }
}

template<int COUT, int KS, bool OUTH>
__global__ __launch_bounds__(256)
void conv_g(const __half* __restrict__ x, const __half* __restrict__ wt,
            const float* __restrict__ bias, void* __restrict__ out,
            int coff, int ctot, int dil)
{
    constexpr int BN = (COUT == 256) ? 128 : 64;
    conv_body<COUT, KS, OUTH>(x, wt, bias, out, coff, ctot, dil,
                              blockIdx.x, blockIdx.y * BN);
}

// Fused 3-dilation query conv: blockIdx.z selects branch (dil 1/3/6)
__global__ __launch_bounds__(256)
void qconv3_g(const __half* __restrict__ x, const __half* __restrict__ wt,
              const float* __restrict__ b1, const float* __restrict__ b2,
              const float* __restrict__ b3, __half* __restrict__ out)
{
    const int z = blockIdx.z;
    const int dil = (z == 0) ? 1 : ((z == 1) ? 3 : 6);
    const float* bias = (z == 0) ? b1 : ((z == 1) ? b2 : b3);
    conv_body<64, 3, true>(x, wt + z * 64 * 2304, bias, out,
                           64 + z * 64, 256, dil, blockIdx.x, 0);
}

// ---------------------------------------------------------------------------
// Per-channel spatial "matmul", double-buffered:
// acc[i,k,c] = sum_j A[b,i,j,c] * Brow(j,k)[c]
// ---------------------------------------------------------------------------
template<bool SWAPB, bool FUSE>
__global__ __launch_bounds__(256)
void pairmm_kernel(const float* __restrict__ A, const float* __restrict__ Bm,
                   float* __restrict__ out, const float* __restrict__ x,
                   const float* __restrict__ gammap)
{
    __shared__ float As[2][8 * 256];
    __shared__ float Bs[2][8 * 256];

    const int c  = threadIdx.x;
    const int i0 = blockIdx.x * 8;
    const int k0 = blockIdx.y * 8;
    const int b  = blockIdx.z;

    float acc[8][8];
    #pragma unroll
    for (int ii = 0; ii < 8; ii++)
        #pragma unroll
        for (int kk = 0; kk < 8; kk++) acc[ii][kk] = 0.f;

    float ar[8], brg[8];
    auto load = [&](int j) {
        #pragma unroll
        for (int r = 0; r < 8; r++) {
            ar[r] = A[(((b*64 + i0 + r)*64 + j) * 256) + c];
            const int brow = SWAPB ? ((b*64 + j)*64 + (k0 + r))
                                   : ((b*64 + (k0 + r))*64 + j);
            brg[r] = Bm[brow * 256 + c];
        }
    };

    load(0);
    for (int j = 0; j < 64; j++) {
        const int st = j & 1;
        #pragma unroll
        for (int r = 0; r < 8; r++) {
            As[st][r*256 + c] = ar[r];
            Bs[st][r*256 + c] = brg[r];
        }
        __syncthreads();
        if (j + 1 < 64) load(j + 1);
        float bv[8];
        #pragma unroll
        for (int kk = 0; kk < 8; kk++) bv[kk] = Bs[st][kk*256 + c];
        #pragma unroll
        for (int ii = 0; ii < 8; ii++) {
            const float av = As[st][ii*256 + c];
            #pragma unroll
            for (int kk = 0; kk < 8; kk++)
                acc[ii][kk] = fmaf(av, bv[kk], acc[ii][kk]);
        }
    }

    const float gm = FUSE ? gammap[0] : 0.f;
    #pragma unroll
    for (int ii = 0; ii < 8; ii++) {
        #pragma unroll
        for (int kk = 0; kk < 8; kk++) {
            const int idx = (((b*64 + i0 + ii)*64 + (k0 + kk)) * 256) + c;
            if (FUSE) out[idx] = gm * acc[ii][kk] + x[idx];
            else      out[idx] = acc[ii][kk];
        }
    }
}

// ---------------------------------------------------------------------------
// Softmax over channels with transposed spatial write
// ---------------------------------------------------------------------------
__global__ __launch_bounds__(256)
void softmax_t_kernel(const float* __restrict__ e, float* __restrict__ at)
{
    const int warp = threadIdx.x / 32;
    const int lane = threadIdx.x % 32;
    const int row  = blockIdx.x * 8 + warp;

    const float* er = &e[row * 256];
    float v[8];
    float m = -1e30f;
    #pragma unroll
    for (int s = 0; s < 8; s++) { v[s] = er[lane + 32*s]; m = fmaxf(m, v[s]); }
    #pragma unroll
    for (int o = 16; o; o >>= 1) m = fmaxf(m, __shfl_xor_sync(0xffffffffu, m, o));
    float sum = 0.f;
    #pragma unroll
    for (int s = 0; s < 8; s++) { v[s] = __expf(v[s] - m); sum += v[s]; }
    #pragma unroll
    for (int o = 16; o; o >>= 1) sum += __shfl_xor_sync(0xffffffffu, sum, o);
    const float inv = 1.0f / sum;

    const int ii  = row % 64;
    const int bjj = row / 64;
    const int jj  = bjj % 64;
    const int b   = bjj / 64;
    float* orow = &at[((b*64 + ii)*64 + jj) * 256];
    #pragma unroll
    for (int s = 0; s < 8; s++) orow[lane + 32*s] = v[s] * inv;
}

// ---------------------------------------------------------------------------
extern "C" void kernel_launch(void* const* d_in, const int* in_sizes, int n_in,
                              void* d_out, int out_size)
{
    const float* x    = (const float*)d_in[0];
    const float* wq   = (const float*)d_in[1];
    const float* bq   = (const float*)d_in[2];
    const float* wq1  = (const float*)d_in[3];
    const float* bq1  = (const float*)d_in[4];
    const float* wq2  = (const float*)d_in[5];
    const float* bq2  = (const float*)d_in[6];
    const float* wq3  = (const float*)d_in[7];
    const float* bq3  = (const float*)d_in[8];
    const float* wq4  = (const float*)d_in[9];
    const float* bq4  = (const float*)d_in[10];
    const float* wk   = (const float*)d_in[11];
    const float* bk   = (const float*)d_in[12];
    const float* wv   = (const float*)d_in[13];
    const float* bv   = (const float*)d_in[14];
    const float* gamma= (const float*)d_in[15];
    float* out = (float*)d_out;

    __half *xh, *k1h, *qcath, *wt;
    float *q, *k, *v, *energy, *attnT;
    cudaGetSymbolAddress((void**)&xh,    g_xh);
    cudaGetSymbolAddress((void**)&k1h,   g_k1h);
    cudaGetSymbolAddress((void**)&qcath, g_qcath);
    cudaGetSymbolAddress((void**)&q,     g_q);
    cudaGetSymbolAddress((void**)&k,     g_k);
    cudaGetSymbolAddress((void**)&v,     g_v);
    cudaGetSymbolAddress((void**)&energy,g_energy);
    cudaGetSymbolAddress((void**)&attnT, g_attnT);
    cudaGetSymbolAddress((void**)&wt,    g_wt);

    // dynamic smem: 3 stages * (128 + BN) * 20 words * 4B
    const int SM256 = 3 * (128 + 128) * 20 * 4;   // 61440
    const int SM64  = 3 * (128 + 64)  * 20 * 4;   // 46080
    cudaFuncSetAttribute(conv_g<256,3,true>,  cudaFuncAttributeMaxDynamicSharedMemorySize, SM256);
    cudaFuncSetAttribute(conv_g<256,3,false>, cudaFuncAttributeMaxDynamicSharedMemorySize, SM256);
    cudaFuncSetAttribute(conv_g<256,1,false>, cudaFuncAttributeMaxDynamicSharedMemorySize, SM256);
    cudaFuncSetAttribute(conv_g<64,1,true>,   cudaFuncAttributeMaxDynamicSharedMemorySize, SM64);
    cudaFuncSetAttribute(qconv3_g,            cudaFuncAttributeMaxDynamicSharedMemorySize, SM64);

    const dim3 cblk(256);

    // pre-passes: x->fp16, all weight transposes (fp16)
    x2h_kernel<<<NPIXTOT * C_ / 4 / 256, 256>>>(x, xh);
    wtrans_kernel<<<(256*2304 + 255)/256, 256>>>(wk,  wt + WT_WK,  256, 2304);
    wtrans_kernel<<<(256*256  + 255)/256, 256>>>(wq4, wt + WT_WQ4, 256, 256);
    wtrans_kernel<<<(256*256  + 255)/256, 256>>>(wv,  wt + WT_WV,  256, 256);
    wtrans_kernel<<<(64*2304  + 255)/256, 256>>>(wq1, wt + WT_WQ1, 64, 2304);
    wtrans_kernel<<<(64*2304  + 255)/256, 256>>>(wq2, wt + WT_WQ2, 64, 2304);
    wtrans_kernel<<<(64*2304  + 255)/256, 256>>>(wq3, wt + WT_WQ3, 64, 2304);
    wtrans_kernel<<<(64*256   + 255)/256, 256>>>(wq,  wt + WT_WQ,  64, 256);

    // k = conv3x3(conv3x3(x)), same weights; k1 kept fp16
    conv_g<256,3,true ><<<dim3(256,2), cblk, SM256>>>(xh,  wt + WT_WK, bk, k1h, 0, 256, 1);
    conv_g<256,3,false><<<dim3(256,2), cblk, SM256>>>(k1h, wt + WT_WK, bk, k,   0, 256, 1);
    // query branch -> qcat (fp16): 1x1 + fused 3-dilation 3x3
    conv_g<64,1,true><<<dim3(256,1), cblk, SM64>>>(xh, wt + WT_WQ, bq, qcath, 0, 256, 1);
    qconv3_g<<<dim3(256,1,3), cblk, SM64>>>(xh, wt + WT_WQ1, bq1, bq2, bq3, qcath);
    // q = 1x1(qcat) fp32, v = 1x1(x) fp32
    conv_g<256,1,false><<<dim3(256,2), cblk, SM256>>>(qcath, wt + WT_WQ4, bq4, q, 0, 256, 1);
    conv_g<256,1,false><<<dim3(256,2), cblk, SM256>>>(xh,    wt + WT_WV,  bv,  v, 0, 256, 1);

    // attention
    pairmm_kernel<true, false><<<dim3(8,8,8), dim3(256)>>>(k, q, energy, nullptr, nullptr);
    softmax_t_kernel<<<NPIXTOT/8, dim3(256)>>>(energy, attnT);
    pairmm_kernel<false, true><<<dim3(8,8,8), dim3(256)>>>(attnT, v, out, x, gamma);
}

// round 14
// speedup vs baseline: 6.0391x; 1.2402x over previous
#include <cuda_runtime.h>
#include <cuda_fp16.h>
#include <cstdint>
#include <cstring>

#define B_ 8
#define H_ 64
#define W_ 64
#define C_ 256
#define NPIXTOT (B_*H_*W_)
#define NELEM (NPIXTOT*C_)

// Scratch (device globals; no allocation allowed) — all 16B-aligned for uint4 access
__device__ __align__(16) __half g_xh[NELEM];     // fp16 input
__device__ __align__(16) __half g_k1h[NELEM];    // fp16 intermediate (k branch)
__device__ __align__(16) __half g_qcath[NELEM];  // fp16 concat (q branch)
__device__ __align__(16) __half g_kh[NELEM];     // conv outputs, (b,pix,c) fp16
__device__ __align__(16) __half g_qh[NELEM];
__device__ __align__(16) __half g_vh[NELEM];
__device__ __align__(16) __half g_kT[NELEM];     // channel-first (b,c,i,j) fp16
__device__ __align__(16) __half g_qT[NELEM];
__device__ __align__(16) __half g_vT[NELEM];
__device__ __align__(16) float  g_E[NELEM];      // energy (b,c,i,k) fp32
__device__ __align__(16) __half g_P[NELEM];      // softmaxed attention (b,c,i,k) fp16
__device__ __align__(16) float  g_O[NELEM];      // attn output (b,c,i,k) fp32
// transposed fp16 weights [cout][ktot]
__device__ __align__(16) __half g_wt[1179648];

#define WT_WK   0
#define WT_WQ4  589824
#define WT_WV   655360
#define WT_WQ1  720896
#define WT_WQ2  868352
#define WT_WQ3  1015808
#define WT_WQ   1163264

__device__ __forceinline__ uint32_t h2u(__half2 h) {
    uint32_t u; memcpy(&u, &h, 4); return u;
}

__device__ __forceinline__ void mma_f16(float* d, const uint32_t* a,
                                        uint32_t b0, uint32_t b1) {
    asm volatile(
        "mma.sync.aligned.m16n8k16.row.col.f32.f16.f16.f32 "
        "{%0,%1,%2,%3}, {%4,%5,%6,%7}, {%8,%9}, {%0,%1,%2,%3};"
        : "+f"(d[0]), "+f"(d[1]), "+f"(d[2]), "+f"(d[3])
        : "r"(a[0]), "r"(a[1]), "r"(a[2]), "r"(a[3]), "r"(b0), "r"(b1));
}
__device__ __forceinline__ void ldsm4(uint32_t* r, uint32_t addr) {
    asm volatile("ldmatrix.sync.aligned.m8n8.x4.shared.b16 {%0,%1,%2,%3}, [%4];"
        : "=r"(r[0]), "=r"(r[1]), "=r"(r[2]), "=r"(r[3]) : "r"(addr));
}
__device__ __forceinline__ void ldsm4t(uint32_t* r, uint32_t addr) {
    asm volatile("ldmatrix.sync.aligned.m8n8.x4.trans.shared.b16 {%0,%1,%2,%3}, [%4];"
        : "=r"(r[0]), "=r"(r[1]), "=r"(r[2]), "=r"(r[3]) : "r"(addr));
}
__device__ __forceinline__ uint32_t scvta(const void* p) {
    return (uint32_t)__cvta_generic_to_shared(p);
}
__device__ __forceinline__ void cp16(uint32_t saddr, const void* gaddr, uint32_t sz) {
    asm volatile("cp.async.ca.shared.global [%0], [%1], 16, %2;"
                 :: "r"(saddr), "l"(gaddr), "r"(sz) : "memory");
}
__device__ __forceinline__ void cp_commit() {
    asm volatile("cp.async.commit_group;" ::: "memory");
}
__device__ __forceinline__ void cp_wait1() {
    asm volatile("cp.async.wait_group 1;" ::: "memory");
}

// ---------------------------------------------------------------------------
// x -> fp16 pre-pass
// ---------------------------------------------------------------------------
__global__ __launch_bounds__(256)
void x2h_kernel(const float* __restrict__ x, __half* __restrict__ xh)
{
    const int i4 = blockIdx.x * 256 + threadIdx.x;
    const float4 v = *(const float4*)&x[i4 * 4];
    __half2* o = (__half2*)&xh[i4 * 4];
    o[0] = __floats2half2_rn(v.x, v.y);
    o[1] = __floats2half2_rn(v.z, v.w);
}

// ---------------------------------------------------------------------------
// Weight transpose + fp16 round: wt[cout][tap*256+ci] = h(w[tap][ci][cout])
// ---------------------------------------------------------------------------
__global__ __launch_bounds__(256)
void wtrans_kernel(const float* __restrict__ w, __half* __restrict__ wt,
                   int COUT, int KTOT)
{
    int idx = blockIdx.x * 256 + threadIdx.x;
    if (idx >= COUT * KTOT) return;
    int co = idx / KTOT;
    int kk = idx - co * KTOT;
    wt[idx] = __float2half_rn(w[kk * COUT + co]);
}

// ---------------------------------------------------------------------------
// Implicit-GEMM conv via mma.sync fp16 (m16n8k16), cp.async 3-stage pipeline.
// ---------------------------------------------------------------------------
template<int COUT, int KS, bool OUTH>
__device__ __forceinline__
void conv_body(const __half* __restrict__ x, const __half* __restrict__ wt,
               const float* __restrict__ bias, void* __restrict__ outp,
               int coff, int ctot, int dil, int tile, int n0)
{
    constexpr int KTOT   = KS * KS * 256;
    constexpr int NCH    = KS * KS * 8;
    constexpr int BN     = (COUT == 256) ? 128 : 64;
    constexpr int WN     = BN / 2;
    constexpr int NA     = WN / 8;
    constexpr int AST    = 20;
    constexpr int AL     = 2;
    constexpr int BL     = BN / 64;
    constexpr int STAGES = 3;

    extern __shared__ uint32_t sm32[];
    uint32_t* Asm = sm32;
    uint32_t* Bsm = sm32 + STAGES * 128 * AST;

    const int tid  = threadIdx.x;
    const int wid  = tid >> 5;
    const int lane = tid & 31;
    const int wm   = wid >> 1;
    const int wn   = wid & 1;
    const int gr   = lane >> 2;
    const int gc   = lane & 3;

    const int b  = tile >> 5;
    const int h0 = (tile & 31) * 2;

    float acc[2][NA][4];
    #pragma unroll
    for (int am = 0; am < 2; am++)
        #pragma unroll
        for (int an = 0; an < NA; an++)
            #pragma unroll
            for (int i = 0; i < 4; i++) acc[am][an][i] = 0.f;

    auto issue = [&](int ch) {
        const int st  = ch % STAGES;
        const int tap = ch >> 3;
        const int c0  = (ch & 7) * 32;
        const int dy  = (tap / KS - KS / 2) * dil;
        const int dx  = (tap % KS - KS / 2) * dil;
        uint32_t* As = Asm + st * 128 * AST;
        uint32_t* Bs = Bsm + st * BN * AST;
        #pragma unroll
        for (int i = 0; i < AL; i++) {
            const int idx = tid + i * 256;
            const int row = idx >> 2;
            const int c16 = idx & 3;
            const int ph  = row >> 6;
            const int pw  = row & 63;
            const int h_in = h0 + ph + dy;
            const int w_in = pw + dx;
            const bool valid = ((unsigned)h_in < 64u) && ((unsigned)w_in < 64u);
            const __half* src = valid
                ? &x[(((b*64 + h_in)*64 + w_in) * 256) + c0 + c16*8] : x;
            cp16(scvta(&As[row * AST + c16 * 4]), src, valid ? 16u : 0u);
        }
        const int koff = tap * 256 + c0;
        #pragma unroll
        for (int i = 0; i < BL; i++) {
            const int idx = tid + i * 256;
            const int row = idx >> 2;
            const int c16 = idx & 3;
            cp16(scvta(&Bs[row * AST + c16 * 4]),
                 &wt[(n0 + row) * KTOT + koff + c16 * 8], 16u);
        }
        cp_commit();
    };

    auto compute = [&](int st) {
        const uint32_t* As = Asm + st * 128 * AST;
        const uint32_t* Bs = Bsm + st * BN * AST;
        #pragma unroll
        for (int s = 0; s < 2; s++) {
            const int kp = s * 8;
            uint32_t afr[2][4];
            #pragma unroll
            for (int am = 0; am < 2; am++) {
                const uint32_t* ap = &As[(wm*32 + am*16 + gr) * AST + kp + gc];
                afr[am][0] = ap[0];
                afr[am][1] = ap[8 * AST];
                afr[am][2] = ap[4];
                afr[am][3] = ap[8 * AST + 4];
            }
            #pragma unroll
            for (int an = 0; an < NA; an++) {
                const uint32_t* bp = &Bs[(wn*WN + an*8 + gr) * AST + kp + gc];
                const uint32_t b0 = bp[0];
                const uint32_t b1 = bp[4];
                #pragma unroll
                for (int am = 0; am < 2; am++)
                    mma_f16(acc[am][an], afr[am], b0, b1);
            }
        }
    };

    issue(0);
    issue(1);
    for (int ch = 0; ch < NCH; ch++) {
        cp_wait1();
        __syncthreads();
        if (ch + 2 < NCH) issue(ch + 2);
        else              cp_commit();
        compute(ch % STAGES);
        __syncthreads();
    }

    #pragma unroll
    for (int am = 0; am < 2; am++) {
        #pragma unroll
        for (int an = 0; an < NA; an++) {
            const int cl = n0 + wn*WN + an*8 + gc*2;
            const float b0v = bias[cl];
            const float b1v = bias[cl + 1];
            #pragma unroll
            for (int half = 0; half < 2; half++) {
                const int mr = wm*32 + am*16 + gr + half*8;
                const int ph = mr >> 6;
                const int pw = mr & 63;
                const int base = (((b*64 + h0 + ph)*64 + pw) * ctot) + coff + cl;
                const float o0 = acc[am][an][half*2 + 0] + b0v;
                const float o1 = acc[am][an][half*2 + 1] + b1v;
                if (OUTH) {
                    *(__half2*)&((__half*)outp)[base] = __floats2half2_rn(o0, o1);
                } else {
                    *(float2*)&((float*)outp)[base] = make_float2(o0, o1);
                }
            }
        }
    }
}

template<int COUT, int KS, bool OUTH>
__global__ __launch_bounds__(256)
void conv_g(const __half* __restrict__ x, const __half* __restrict__ wt,
            const float* __restrict__ bias, void* __restrict__ out,
            int coff, int ctot, int dil)
{
    constexpr int BN = (COUT == 256) ? 128 : 64;
    conv_body<COUT, KS, OUTH>(x, wt, bias, out, coff, ctot, dil,
                              blockIdx.x, blockIdx.y * BN);
}

__global__ __launch_bounds__(256)
void qconv3_g(const __half* __restrict__ x, const __half* __restrict__ wt,
              const float* __restrict__ b1, const float* __restrict__ b2,
              const float* __restrict__ b3, __half* __restrict__ out)
{
    const int z = blockIdx.z;
    const int dil = (z == 0) ? 1 : ((z == 1) ? 3 : 6);
    const float* bias = (z == 0) ? b1 : ((z == 1) ? b2 : b3);
    conv_body<64, 3, true>(x, wt + z * 64 * 2304, bias, out,
                           64 + z * 64, 256, dil, blockIdx.x, 0);
}

// ---------------------------------------------------------------------------
// fp16 transpose: (b, 4096 pix, 256 c) -> (b, 256 c, 4096 pix)
// 64x64 tiles via smem (pad to 72 halves/row = 144B, 16B-aligned rows).
// ---------------------------------------------------------------------------
__global__ __launch_bounds__(256)
void transp_h(const __half* __restrict__ in, __half* __restrict__ outp)
{
    __shared__ __align__(16) __half t[64 * 72];
    const int b  = blockIdx.z;
    const int p0 = blockIdx.x * 64;
    const int c0 = blockIdx.y * 64;
    const int tid = threadIdx.x;

    #pragma unroll
    for (int i = 0; i < 2; i++) {
        const int idx = tid + i * 256;       // 16B units (512 total)
        const int r  = idx >> 3;
        const int c8 = idx & 7;
        *(uint4*)&t[r * 72 + c8 * 8] =
            *(const uint4*)&in[((b * 4096) + p0 + r) * 256 + c0 + c8 * 8];
    }
    __syncthreads();

    const int c  = tid & 63;
    const int pg = tid >> 6;                 // 4 groups of 16 pix
    uint4 o0, o1;
    o0.x = h2u(__halves2half2(t[(pg*16+ 0)*72 + c], t[(pg*16+ 1)*72 + c]));
    o0.y = h2u(__halves2half2(t[(pg*16+ 2)*72 + c], t[(pg*16+ 3)*72 + c]));
    o0.z = h2u(__halves2half2(t[(pg*16+ 4)*72 + c], t[(pg*16+ 5)*72 + c]));
    o0.w = h2u(__halves2half2(t[(pg*16+ 6)*72 + c], t[(pg*16+ 7)*72 + c]));
    o1.x = h2u(__halves2half2(t[(pg*16+ 8)*72 + c], t[(pg*16+ 9)*72 + c]));
    o1.y = h2u(__halves2half2(t[(pg*16+10)*72 + c], t[(pg*16+11)*72 + c]));
    o1.z = h2u(__halves2half2(t[(pg*16+12)*72 + c], t[(pg*16+13)*72 + c]));
    o1.w = h2u(__halves2half2(t[(pg*16+14)*72 + c], t[(pg*16+15)*72 + c]));
    __half* o = &outp[((b * 256) + c0 + c) * 4096 + p0 + pg * 16];
    *(uint4*)&o[0] = o0;
    *(uint4*)&o[8] = o1;
}

// ---------------------------------------------------------------------------
// gemm1: E_c[i,k2] = sum_j kT_c[i,j] * qT_c[j,k2]   (per b,c: 64x64x64)
// A: ldmatrix non-trans from kT; B: ldmatrix trans from qT.
// ---------------------------------------------------------------------------
__global__ __launch_bounds__(128)
void attn_gemm1(const __half* __restrict__ kT, const __half* __restrict__ qT,
                float* __restrict__ E)
{
    __shared__ __align__(16) __half Ks[64 * 72];
    __shared__ __align__(16) __half Qs[64 * 72];
    const int bc   = blockIdx.x;
    const int tid  = threadIdx.x;
    const int wid  = tid >> 5;
    const int lane = tid & 31;

    const __half* kg = kT + bc * 4096;
    const __half* qg = qT + bc * 4096;
    #pragma unroll
    for (int i = 0; i < 4; i++) {
        const int idx = tid + i * 128;
        const int r  = idx >> 3;
        const int c8 = idx & 7;
        *(uint4*)&Ks[r * 72 + c8 * 8] = *(const uint4*)&kg[r * 64 + c8 * 8];
        *(uint4*)&Qs[r * 72 + c8 * 8] = *(const uint4*)&qg[r * 64 + c8 * 8];
    }
    __syncthreads();

    float acc[8][4];
    #pragma unroll
    for (int i = 0; i < 8; i++)
        #pragma unroll
        for (int j = 0; j < 4; j++) acc[i][j] = 0.f;

    const int i0   = wid * 16;
    const int arow = (lane & 7) + ((lane & 8) ? 8 : 0);   // A: row within m16
    const int acol = (lane & 16) ? 8 : 0;                 // A: k offset
    const int brow = (lane & 7) + ((lane & 8) ? 8 : 0);   // B(trans): j row
    const int bcol = (lane & 16) ? 8 : 0;                 // B(trans): n offset

    #pragma unroll
    for (int kp = 0; kp < 4; kp++) {                      // j in chunks of 16
        uint32_t a[4];
        ldsm4(a, scvta(&Ks[(i0 + arow) * 72 + kp * 16 + acol]));
        #pragma unroll
        for (int np = 0; np < 4; np++) {                  // n in chunks of 16
            uint32_t bf[4];
            ldsm4t(bf, scvta(&Qs[(kp * 16 + brow) * 72 + np * 16 + bcol]));
            mma_f16(acc[np * 2 + 0], a, bf[0], bf[1]);
            mma_f16(acc[np * 2 + 1], a, bf[2], bf[3]);
        }
    }

    float* eb = E + bc * 4096;
    const int r0 = i0 + (lane >> 2);
    const int cb = (lane & 3) * 2;
    #pragma unroll
    for (int na = 0; na < 8; na++) {
        const int col = na * 8 + cb;
        *(float2*)&eb[r0 * 64 + col]       = make_float2(acc[na][0], acc[na][1]);
        *(float2*)&eb[(r0 + 8) * 64 + col] = make_float2(acc[na][2], acc[na][3]);
    }
}

// ---------------------------------------------------------------------------
// Softmax over channel axis: P[b,c,ik] = softmax_c(E[b,:,ik]) as fp16
// ---------------------------------------------------------------------------
__global__ __launch_bounds__(128)
void softmax_c_kernel(const float* __restrict__ E, __half* __restrict__ P)
{
    const int b  = blockIdx.x >> 5;
    const int ik = ((blockIdx.x & 31) * 128) + threadIdx.x;
    const float* e = E + (size_t)b * 256 * 4096 + ik;
    float m = -1e30f;
    #pragma unroll 8
    for (int c = 0; c < 256; c++) m = fmaxf(m, e[c * 4096]);
    float s = 0.f;
    #pragma unroll 8
    for (int c = 0; c < 256; c++) s += __expf(e[c * 4096] - m);
    const float inv = 1.0f / s;
    __half* p = P + (size_t)b * 256 * 4096 + ik;
    #pragma unroll 8
    for (int c = 0; c < 256; c++)
        p[c * 4096] = __float2half(__expf(e[c * 4096] - m) * inv);
}

// ---------------------------------------------------------------------------
// gemm2: O_c[i2,k2] = sum_j P_c[j,i2] * vT_c[k2,j]
// A: ldmatrix TRANS from P; B: ldmatrix non-trans from vT.
// ---------------------------------------------------------------------------
__global__ __launch_bounds__(128)
void attn_gemm2(const __half* __restrict__ P, const __half* __restrict__ vT,
                float* __restrict__ O)
{
    __shared__ __align__(16) __half Ps[64 * 72];
    __shared__ __align__(16) __half Vs[64 * 72];
    const int bc   = blockIdx.x;
    const int tid  = threadIdx.x;
    const int wid  = tid >> 5;
    const int lane = tid & 31;

    const __half* pg = P  + bc * 4096;
    const __half* vg = vT + bc * 4096;
    #pragma unroll
    for (int i = 0; i < 4; i++) {
        const int idx = tid + i * 128;
        const int r  = idx >> 3;
        const int c8 = idx & 7;
        *(uint4*)&Ps[r * 72 + c8 * 8] = *(const uint4*)&pg[r * 64 + c8 * 8];
        *(uint4*)&Vs[r * 72 + c8 * 8] = *(const uint4*)&vg[r * 64 + c8 * 8];
    }
    __syncthreads();

    float acc[8][4];
    #pragma unroll
    for (int i = 0; i < 8; i++)
        #pragma unroll
        for (int j = 0; j < 4; j++) acc[i][j] = 0.f;

    const int i0   = wid * 16;
    // A (trans): stored rows = j, cols = i.
    const int arow = (lane & 7) + ((lane & 16) ? 8 : 0);
    const int acol = i0 + ((lane & 8) ? 8 : 0);
    // B (non-trans): rows = n (k2), cols = j.
    const int brow = (lane & 7) + ((lane & 16) ? 8 : 0);
    const int bcol = (lane & 8) ? 8 : 0;

    #pragma unroll
    for (int kp = 0; kp < 4; kp++) {                      // j chunks
        uint32_t a[4];
        ldsm4t(a, scvta(&Ps[(kp * 16 + arow) * 72 + acol]));
        #pragma unroll
        for (int np = 0; np < 4; np++) {                  // n chunks of 16
            uint32_t bf[4];
            ldsm4(bf, scvta(&Vs[(np * 16 + brow) * 72 + kp * 16 + bcol]));
            mma_f16(acc[np * 2 + 0], a, bf[0], bf[1]);
            mma_f16(acc[np * 2 + 1], a, bf[2], bf[3]);
        }
    }

    float* ob = O + bc * 4096;
    const int r0 = i0 + (lane >> 2);
    const int cb = (lane & 3) * 2;
    #pragma unroll
    for (int na = 0; na < 8; na++) {
        const int col = na * 8 + cb;
        *(float2*)&ob[r0 * 64 + col]       = make_float2(acc[na][0], acc[na][1]);
        *(float2*)&ob[(r0 + 8) * 64 + col] = make_float2(acc[na][2], acc[na][3]);
    }
}

// ---------------------------------------------------------------------------
// Final: out[b,ik,c] = gamma * O[b,c,ik] + x[b,ik,c]  (tile-transposed)
// smem row stride 68 floats = 272B (16B-aligned; stride 65 was the
// misaligned-address bug).
// ---------------------------------------------------------------------------
__global__ __launch_bounds__(256)
void final_merge(const float* __restrict__ O, const float* __restrict__ x,
                 const float* __restrict__ gammap, float* __restrict__ outp)
{
    __shared__ __align__(16) float t[64 * 68];
    const int b   = blockIdx.z;
    const int ik0 = blockIdx.x * 64;
    const int c0  = blockIdx.y * 64;
    const int tid = threadIdx.x;

    #pragma unroll
    for (int i = 0; i < 4; i++) {
        const int idx = tid + i * 256;         // float4 units (1024 total)
        const int r   = idx >> 4;              // c row
        const int c16 = idx & 15;
        *(float4*)&t[r * 68 + c16 * 4] =
            *(const float4*)&O[((size_t)(b * 256 + c0 + r)) * 4096 + ik0 + c16 * 4];
    }
    __syncthreads();

    const float gm = gammap[0];
    const int ik = tid & 63;
    const int cg = tid >> 6;                   // 4 groups of 16 c
    const int gbase = ((b * 4096) + ik0 + ik) * 256 + c0 + cg * 16;
    #pragma unroll
    for (int i = 0; i < 16; i += 4) {
        const int c = cg * 16 + i;
        const float4 xv = *(const float4*)&x[gbase + i];
        float4 o;
        o.x = gm * t[(c + 0) * 68 + ik] + xv.x;
        o.y = gm * t[(c + 1) * 68 + ik] + xv.y;
        o.z = gm * t[(c + 2) * 68 + ik] + xv.z;
        o.w = gm * t[(c + 3) * 68 + ik] + xv.w;
        *(float4*)&outp[gbase + i] = o;
    }
}

// ---------------------------------------------------------------------------
extern "C" void kernel_launch(void* const* d_in, const int* in_sizes, int n_in,
                              void* d_out, int out_size)
{
    const float* x    = (const float*)d_in[0];
    const float* wq   = (const float*)d_in[1];
    const float* bq   = (const float*)d_in[2];
    const float* wq1  = (const float*)d_in[3];
    const float* bq1  = (const float*)d_in[4];
    const float* wq2  = (const float*)d_in[5];
    const float* bq2  = (const float*)d_in[6];
    const float* wq3  = (const float*)d_in[7];
    const float* bq3  = (const float*)d_in[8];
    const float* wq4  = (const float*)d_in[9];
    const float* bq4  = (const float*)d_in[10];
    const float* wk   = (const float*)d_in[11];
    const float* bk   = (const float*)d_in[12];
    const float* wv   = (const float*)d_in[13];
    const float* bv   = (const float*)d_in[14];
    const float* gamma= (const float*)d_in[15];
    float* out = (float*)d_out;

    __half *xh, *k1h, *qcath, *kh, *qh, *vh, *kT, *qT, *vT, *P, *wt;
    float *E, *O;
    cudaGetSymbolAddress((void**)&xh,    g_xh);
    cudaGetSymbolAddress((void**)&k1h,   g_k1h);
    cudaGetSymbolAddress((void**)&qcath, g_qcath);
    cudaGetSymbolAddress((void**)&kh,    g_kh);
    cudaGetSymbolAddress((void**)&qh,    g_qh);
    cudaGetSymbolAddress((void**)&vh,    g_vh);
    cudaGetSymbolAddress((void**)&kT,    g_kT);
    cudaGetSymbolAddress((void**)&qT,    g_qT);
    cudaGetSymbolAddress((void**)&vT,    g_vT);
    cudaGetSymbolAddress((void**)&E,     g_E);
    cudaGetSymbolAddress((void**)&P,     g_P);
    cudaGetSymbolAddress((void**)&O,     g_O);
    cudaGetSymbolAddress((void**)&wt,    g_wt);

    const int SM256 = 3 * (128 + 128) * 20 * 4;   // 61440
    const int SM64  = 3 * (128 + 64)  * 20 * 4;   // 46080
    cudaFuncSetAttribute(conv_g<256,3,true>, cudaFuncAttributeMaxDynamicSharedMemorySize, SM256);
    cudaFuncSetAttribute(conv_g<256,1,true>, cudaFuncAttributeMaxDynamicSharedMemorySize, SM256);
    cudaFuncSetAttribute(conv_g<64,1,true>,  cudaFuncAttributeMaxDynamicSharedMemorySize, SM64);
    cudaFuncSetAttribute(qconv3_g,           cudaFuncAttributeMaxDynamicSharedMemorySize, SM64);

    const dim3 cblk(256);

    // pre-passes
    x2h_kernel<<<NELEM / 4 / 256, 256>>>(x, xh);
    wtrans_kernel<<<(256*2304 + 255)/256, 256>>>(wk,  wt + WT_WK,  256, 2304);
    wtrans_kernel<<<(256*256  + 255)/256, 256>>>(wq4, wt + WT_WQ4, 256, 256);
    wtrans_kernel<<<(256*256  + 255)/256, 256>>>(wv,  wt + WT_WV,  256, 256);
    wtrans_kernel<<<(64*2304  + 255)/256, 256>>>(wq1, wt + WT_WQ1, 64, 2304);
    wtrans_kernel<<<(64*2304  + 255)/256, 256>>>(wq2, wt + WT_WQ2, 64, 2304);
    wtrans_kernel<<<(64*2304  + 255)/256, 256>>>(wq3, wt + WT_WQ3, 64, 2304);
    wtrans_kernel<<<(64*256   + 255)/256, 256>>>(wq,  wt + WT_WQ,  64, 256);

    // convs (all fp16 out)
    conv_g<256,3,true><<<dim3(256,2), cblk, SM256>>>(xh,  wt + WT_WK, bk, k1h, 0, 256, 1);
    conv_g<256,3,true><<<dim3(256,2), cblk, SM256>>>(k1h, wt + WT_WK, bk, kh,  0, 256, 1);
    conv_g<64,1,true><<<dim3(256,1), cblk, SM64>>>(xh, wt + WT_WQ, bq, qcath, 0, 256, 1);
    qconv3_g<<<dim3(256,1,3), cblk, SM64>>>(xh, wt + WT_WQ1, bq1, bq2, bq3, qcath);
    conv_g<256,1,true><<<dim3(256,2), cblk, SM256>>>(qcath, wt + WT_WQ4, bq4, qh, 0, 256, 1);
    conv_g<256,1,true><<<dim3(256,2), cblk, SM256>>>(xh,    wt + WT_WV,  bv,  vh, 0, 256, 1);

    // attention (MMA path)
    transp_h<<<dim3(64,4,8), 256>>>(kh, kT);
    transp_h<<<dim3(64,4,8), 256>>>(qh, qT);
    transp_h<<<dim3(64,4,8), 256>>>(vh, vT);
    attn_gemm1<<<2048, 128>>>(kT, qT, E);
    softmax_c_kernel<<<256, 128>>>(E, P);
    attn_gemm2<<<2048, 128>>>(P, vT, O);
    final_merge<<<dim3(64,4,8), 256>>>(O, x, gamma, out);
}

// round 15
// speedup vs baseline: 6.3785x; 1.0562x over previous
#include <cuda_runtime.h>
#include <cuda_fp16.h>
#include <cstdint>
#include <cstring>

#define B_ 8
#define H_ 64
#define W_ 64
#define C_ 256
#define NPIXTOT (B_*H_*W_)
#define NELEM (NPIXTOT*C_)

// Scratch (device globals; no allocation allowed) — all 16B-aligned for uint4 access
__device__ __align__(16) __half g_xh[NELEM];     // fp16 input
__device__ __align__(16) __half g_k1h[NELEM];    // fp16 intermediate (k branch)
__device__ __align__(16) __half g_qcath[NELEM];  // fp16 concat (q branch)
__device__ __align__(16) __half g_kh[NELEM];     // conv outputs, (b,pix,c) fp16
__device__ __align__(16) __half g_qh[NELEM];
__device__ __align__(16) __half g_vh[NELEM];
__device__ __align__(16) __half g_kT[NELEM];     // channel-first (b,c,i,j) fp16
__device__ __align__(16) __half g_qT[NELEM];
__device__ __align__(16) __half g_vT[NELEM];
__device__ __align__(16) float  g_E[NELEM];      // energy (b,c,i,k) fp32
__device__ __align__(16) __half g_P[NELEM];      // softmaxed attention (b,c,i,k) fp16
__device__ __align__(16) float  g_O[NELEM];      // attn output (b,c,i,k) fp32
// transposed fp16 weights [cout][ktot]
__device__ __align__(16) __half g_wt[1179648];

#define WT_WK   0
#define WT_WQ4  589824
#define WT_WV   655360
#define WT_WQ1  720896
#define WT_WQ2  868352
#define WT_WQ3  1015808
#define WT_WQ   1163264

__device__ __forceinline__ uint32_t h2u(__half2 h) {
    uint32_t u; memcpy(&u, &h, 4); return u;
}

__device__ __forceinline__ void mma_f16(float* d, const uint32_t* a,
                                        uint32_t b0, uint32_t b1) {
    asm volatile(
        "mma.sync.aligned.m16n8k16.row.col.f32.f16.f16.f32 "
        "{%0,%1,%2,%3}, {%4,%5,%6,%7}, {%8,%9}, {%0,%1,%2,%3};"
        : "+f"(d[0]), "+f"(d[1]), "+f"(d[2]), "+f"(d[3])
        : "r"(a[0]), "r"(a[1]), "r"(a[2]), "r"(a[3]), "r"(b0), "r"(b1));
}
__device__ __forceinline__ void ldsm4(uint32_t* r, uint32_t addr) {
    asm volatile("ldmatrix.sync.aligned.m8n8.x4.shared.b16 {%0,%1,%2,%3}, [%4];"
        : "=r"(r[0]), "=r"(r[1]), "=r"(r[2]), "=r"(r[3]) : "r"(addr));
}
__device__ __forceinline__ void ldsm4t(uint32_t* r, uint32_t addr) {
    asm volatile("ldmatrix.sync.aligned.m8n8.x4.trans.shared.b16 {%0,%1,%2,%3}, [%4];"
        : "=r"(r[0]), "=r"(r[1]), "=r"(r[2]), "=r"(r[3]) : "r"(addr));
}
__device__ __forceinline__ uint32_t scvta(const void* p) {
    return (uint32_t)__cvta_generic_to_shared(p);
}
__device__ __forceinline__ void cp16(uint32_t saddr, const void* gaddr, uint32_t sz) {
    asm volatile("cp.async.ca.shared.global [%0], [%1], 16, %2;"
                 :: "r"(saddr), "l"(gaddr), "r"(sz) : "memory");
}
__device__ __forceinline__ void cp_commit() {
    asm volatile("cp.async.commit_group;" ::: "memory");
}
__device__ __forceinline__ void cp_wait1() {
    asm volatile("cp.async.wait_group 1;" ::: "memory");
}

// ---------------------------------------------------------------------------
// x -> fp16 pre-pass
// ---------------------------------------------------------------------------
__global__ __launch_bounds__(256)
void x2h_kernel(const float* __restrict__ x, __half* __restrict__ xh)
{
    const int i4 = blockIdx.x * 256 + threadIdx.x;
    const float4 v = *(const float4*)&x[i4 * 4];
    __half2* o = (__half2*)&xh[i4 * 4];
    o[0] = __floats2half2_rn(v.x, v.y);
    o[1] = __floats2half2_rn(v.z, v.w);
}

// ---------------------------------------------------------------------------
// ALL weight transposes fused: one segmented kernel.
// wt[base + co*KTOT + kk] = h(src[kk*COUT + co])
// ---------------------------------------------------------------------------
__global__ __launch_bounds__(256)
void wtrans_all(const float* __restrict__ wk,  const float* __restrict__ wq4,
                const float* __restrict__ wv,  const float* __restrict__ wq1,
                const float* __restrict__ wq2, const float* __restrict__ wq3,
                const float* __restrict__ wq,  __half* __restrict__ wt)
{
    const int idx = blockIdx.x * 256 + threadIdx.x;   // < 1179648
    const float* src; int base, COUT, KTOT;
    if      (idx < 655360)  { if (idx < 589824) { src=wk;  base=0;       COUT=256; KTOT=2304; }
                              else              { src=wq4; base=589824;  COUT=256; KTOT=256;  } }
    else if (idx < 868352)  { if (idx < 720896) { src=wv;  base=655360;  COUT=256; KTOT=256;  }
                              else              { src=wq1; base=720896;  COUT=64;  KTOT=2304; } }
    else if (idx < 1163264) { if (idx < 1015808){ src=wq2; base=868352;  COUT=64;  KTOT=2304; }
                              else              { src=wq3; base=1015808; COUT=64;  KTOT=2304; } }
    else                    {                     src=wq;  base=1163264; COUT=64;  KTOT=256;  }
    const int l  = idx - base;
    const int co = l / KTOT;
    const int kk = l - co * KTOT;
    wt[idx] = __float2half_rn(src[kk * COUT + co]);
}

// ---------------------------------------------------------------------------
// Implicit-GEMM conv via mma.sync fp16 (m16n8k16), cp.async 3-stage pipeline.
// ---------------------------------------------------------------------------
template<int COUT, int KS, bool OUTH>
__device__ __forceinline__
void conv_body(const __half* __restrict__ x, const __half* __restrict__ wt,
               const float* __restrict__ bias, void* __restrict__ outp,
               int coff, int ctot, int dil, int tile, int n0)
{
    constexpr int KTOT   = KS * KS * 256;
    constexpr int NCH    = KS * KS * 8;
    constexpr int BN     = (COUT == 256) ? 128 : 64;
    constexpr int WN     = BN / 2;
    constexpr int NA     = WN / 8;
    constexpr int AST    = 20;
    constexpr int AL     = 2;
    constexpr int BL     = BN / 64;
    constexpr int STAGES = 3;

    extern __shared__ uint32_t sm32[];
    uint32_t* Asm = sm32;
    uint32_t* Bsm = sm32 + STAGES * 128 * AST;

    const int tid  = threadIdx.x;
    const int wid  = tid >> 5;
    const int lane = tid & 31;
    const int wm   = wid >> 1;
    const int wn   = wid & 1;
    const int gr   = lane >> 2;
    const int gc   = lane & 3;

    const int b  = tile >> 5;
    const int h0 = (tile & 31) * 2;

    float acc[2][NA][4];
    #pragma unroll
    for (int am = 0; am < 2; am++)
        #pragma unroll
        for (int an = 0; an < NA; an++)
            #pragma unroll
            for (int i = 0; i < 4; i++) acc[am][an][i] = 0.f;

    auto issue = [&](int ch) {
        const int st  = ch % STAGES;
        const int tap = ch >> 3;
        const int c0  = (ch & 7) * 32;
        const int dy  = (tap / KS - KS / 2) * dil;
        const int dx  = (tap % KS - KS / 2) * dil;
        uint32_t* As = Asm + st * 128 * AST;
        uint32_t* Bs = Bsm + st * BN * AST;
        #pragma unroll
        for (int i = 0; i < AL; i++) {
            const int idx = tid + i * 256;
            const int row = idx >> 2;
            const int c16 = idx & 3;
            const int ph  = row >> 6;
            const int pw  = row & 63;
            const int h_in = h0 + ph + dy;
            const int w_in = pw + dx;
            const bool valid = ((unsigned)h_in < 64u) && ((unsigned)w_in < 64u);
            const __half* src = valid
                ? &x[(((b*64 + h_in)*64 + w_in) * 256) + c0 + c16*8] : x;
            cp16(scvta(&As[row * AST + c16 * 4]), src, valid ? 16u : 0u);
        }
        const int koff = tap * 256 + c0;
        #pragma unroll
        for (int i = 0; i < BL; i++) {
            const int idx = tid + i * 256;
            const int row = idx >> 2;
            const int c16 = idx & 3;
            cp16(scvta(&Bs[row * AST + c16 * 4]),
                 &wt[(n0 + row) * KTOT + koff + c16 * 8], 16u);
        }
        cp_commit();
    };

    auto compute = [&](int st) {
        const uint32_t* As = Asm + st * 128 * AST;
        const uint32_t* Bs = Bsm + st * BN * AST;
        #pragma unroll
        for (int s = 0; s < 2; s++) {
            const int kp = s * 8;
            uint32_t afr[2][4];
            #pragma unroll
            for (int am = 0; am < 2; am++) {
                const uint32_t* ap = &As[(wm*32 + am*16 + gr) * AST + kp + gc];
                afr[am][0] = ap[0];
                afr[am][1] = ap[8 * AST];
                afr[am][2] = ap[4];
                afr[am][3] = ap[8 * AST + 4];
            }
            #pragma unroll
            for (int an = 0; an < NA; an++) {
                const uint32_t* bp = &Bs[(wn*WN + an*8 + gr) * AST + kp + gc];
                const uint32_t b0 = bp[0];
                const uint32_t b1 = bp[4];
                #pragma unroll
                for (int am = 0; am < 2; am++)
                    mma_f16(acc[am][an], afr[am], b0, b1);
            }
        }
    };

    issue(0);
    issue(1);
    for (int ch = 0; ch < NCH; ch++) {
        cp_wait1();
        __syncthreads();
        if (ch + 2 < NCH) issue(ch + 2);
        else              cp_commit();
        compute(ch % STAGES);
        __syncthreads();
    }

    #pragma unroll
    for (int am = 0; am < 2; am++) {
        #pragma unroll
        for (int an = 0; an < NA; an++) {
            const int cl = n0 + wn*WN + an*8 + gc*2;
            const float b0v = bias[cl];
            const float b1v = bias[cl + 1];
            #pragma unroll
            for (int half = 0; half < 2; half++) {
                const int mr = wm*32 + am*16 + gr + half*8;
                const int ph = mr >> 6;
                const int pw = mr & 63;
                const int base = (((b*64 + h0 + ph)*64 + pw) * ctot) + coff + cl;
                const float o0 = acc[am][an][half*2 + 0] + b0v;
                const float o1 = acc[am][an][half*2 + 1] + b1v;
                if (OUTH) {
                    *(__half2*)&((__half*)outp)[base] = __floats2half2_rn(o0, o1);
                } else {
                    *(float2*)&((float*)outp)[base] = make_float2(o0, o1);
                }
            }
        }
    }
}

template<int COUT, int KS, bool OUTH>
__global__ __launch_bounds__(256)
void conv_g(const __half* __restrict__ x, const __half* __restrict__ wt,
            const float* __restrict__ bias, void* __restrict__ out,
            int coff, int ctot, int dil)
{
    constexpr int BN = (COUT == 256) ? 128 : 64;
    conv_body<COUT, KS, OUTH>(x, wt, bias, out, coff, ctot, dil,
                              blockIdx.x, blockIdx.y * BN);
}

__global__ __launch_bounds__(256)
void qconv3_g(const __half* __restrict__ x, const __half* __restrict__ wt,
              const float* __restrict__ b1, const float* __restrict__ b2,
              const float* __restrict__ b3, __half* __restrict__ out)
{
    const int z = blockIdx.z;
    const int dil = (z == 0) ? 1 : ((z == 1) ? 3 : 6);
    const float* bias = (z == 0) ? b1 : ((z == 1) ? b2 : b3);
    conv_body<64, 3, true>(x, wt + z * 64 * 2304, bias, out,
                           64 + z * 64, 256, dil, blockIdx.x, 0);
}

// ---------------------------------------------------------------------------
// fp16 transpose, 3 tensors in one launch (z = tensor*8 + b):
// (b, 4096 pix, 256 c) -> (b, 256 c, 4096 pix); 64x64 tiles, rows padded to 72.
// ---------------------------------------------------------------------------
__global__ __launch_bounds__(256)
void transp3_h(const __half* __restrict__ kh, const __half* __restrict__ qh,
               const __half* __restrict__ vh, __half* __restrict__ kT,
               __half* __restrict__ qT, __half* __restrict__ vT)
{
    __shared__ __align__(16) __half t[64 * 72];
    const int z  = blockIdx.z;
    const int tn = z >> 3;
    const int b  = z & 7;
    const __half* in   = (tn == 0) ? kh : ((tn == 1) ? qh : vh);
    __half*       outp = (tn == 0) ? kT : ((tn == 1) ? qT : vT);
    const int p0 = blockIdx.x * 64;
    const int c0 = blockIdx.y * 64;
    const int tid = threadIdx.x;

    #pragma unroll
    for (int i = 0; i < 2; i++) {
        const int idx = tid + i * 256;       // 16B units (512 total)
        const int r  = idx >> 3;
        const int c8 = idx & 7;
        *(uint4*)&t[r * 72 + c8 * 8] =
            *(const uint4*)&in[((b * 4096) + p0 + r) * 256 + c0 + c8 * 8];
    }
    __syncthreads();

    const int c  = tid & 63;
    const int pg = tid >> 6;                 // 4 groups of 16 pix
    uint4 o0, o1;
    o0.x = h2u(__halves2half2(t[(pg*16+ 0)*72 + c], t[(pg*16+ 1)*72 + c]));
    o0.y = h2u(__halves2half2(t[(pg*16+ 2)*72 + c], t[(pg*16+ 3)*72 + c]));
    o0.z = h2u(__halves2half2(t[(pg*16+ 4)*72 + c], t[(pg*16+ 5)*72 + c]));
    o0.w = h2u(__halves2half2(t[(pg*16+ 6)*72 + c], t[(pg*16+ 7)*72 + c]));
    o1.x = h2u(__halves2half2(t[(pg*16+ 8)*72 + c], t[(pg*16+ 9)*72 + c]));
    o1.y = h2u(__halves2half2(t[(pg*16+10)*72 + c], t[(pg*16+11)*72 + c]));
    o1.z = h2u(__halves2half2(t[(pg*16+12)*72 + c], t[(pg*16+13)*72 + c]));
    o1.w = h2u(__halves2half2(t[(pg*16+14)*72 + c], t[(pg*16+15)*72 + c]));
    __half* o = &outp[((b * 256) + c0 + c) * 4096 + p0 + pg * 16];
    *(uint4*)&o[0] = o0;
    *(uint4*)&o[8] = o1;
}

// ---------------------------------------------------------------------------
// gemm1: E_c[i,k2] = sum_j kT_c[i,j] * qT_c[j,k2]   (per b,c: 64x64x64)
// A: ldmatrix non-trans from kT; B: ldmatrix trans from qT.
// ---------------------------------------------------------------------------
__global__ __launch_bounds__(128)
void attn_gemm1(const __half* __restrict__ kT, const __half* __restrict__ qT,
                float* __restrict__ E)
{
    __shared__ __align__(16) __half Ks[64 * 72];
    __shared__ __align__(16) __half Qs[64 * 72];
    const int bc   = blockIdx.x;
    const int tid  = threadIdx.x;
    const int wid  = tid >> 5;
    const int lane = tid & 31;

    const __half* kg = kT + bc * 4096;
    const __half* qg = qT + bc * 4096;
    #pragma unroll
    for (int i = 0; i < 4; i++) {
        const int idx = tid + i * 128;
        const int r  = idx >> 3;
        const int c8 = idx & 7;
        *(uint4*)&Ks[r * 72 + c8 * 8] = *(const uint4*)&kg[r * 64 + c8 * 8];
        *(uint4*)&Qs[r * 72 + c8 * 8] = *(const uint4*)&qg[r * 64 + c8 * 8];
    }
    __syncthreads();

    float acc[8][4];
    #pragma unroll
    for (int i = 0; i < 8; i++)
        #pragma unroll
        for (int j = 0; j < 4; j++) acc[i][j] = 0.f;

    const int i0   = wid * 16;
    const int arow = (lane & 7) + ((lane & 8) ? 8 : 0);   // A: row within m16
    const int acol = (lane & 16) ? 8 : 0;                 // A: k offset
    const int brow = (lane & 7) + ((lane & 8) ? 8 : 0);   // B(trans): j row
    const int bcol = (lane & 16) ? 8 : 0;                 // B(trans): n offset

    #pragma unroll
    for (int kp = 0; kp < 4; kp++) {                      // j in chunks of 16
        uint32_t a[4];
        ldsm4(a, scvta(&Ks[(i0 + arow) * 72 + kp * 16 + acol]));
        #pragma unroll
        for (int np = 0; np < 4; np++) {                  // n in chunks of 16
            uint32_t bf[4];
            ldsm4t(bf, scvta(&Qs[(kp * 16 + brow) * 72 + np * 16 + bcol]));
            mma_f16(acc[np * 2 + 0], a, bf[0], bf[1]);
            mma_f16(acc[np * 2 + 1], a, bf[2], bf[3]);
        }
    }

    float* eb = E + bc * 4096;
    const int r0 = i0 + (lane >> 2);
    const int cb = (lane & 3) * 2;
    #pragma unroll
    for (int na = 0; na < 8; na++) {
        const int col = na * 8 + cb;
        *(float2*)&eb[r0 * 64 + col]       = make_float2(acc[na][0], acc[na][1]);
        *(float2*)&eb[(r0 + 8) * 64 + col] = make_float2(acc[na][2], acc[na][3]);
    }
}

// ---------------------------------------------------------------------------
// Softmax over channel axis, block-cooperative (8 c-groups x 32 ik / block):
// P[b,c,ik] = softmax_c(E[b,:,ik]) as fp16. One memory pass, values in regs.
// ---------------------------------------------------------------------------
__global__ __launch_bounds__(256)
void softmax_c_kernel(const float* __restrict__ E, __half* __restrict__ P)
{
    __shared__ float red[8][32];
    const int b   = blockIdx.x >> 7;                 // 1024 blocks
    const int ik0 = (blockIdx.x & 127) * 32;
    const int ikl = threadIdx.x & 31;
    const int cg  = threadIdx.x >> 5;
    const int ik  = ik0 + ikl;

    const float* e = E + ((size_t)(b * 256 + cg * 32)) * 4096 + ik;
    float v[32];
    float m = -1e30f;
    #pragma unroll
    for (int j = 0; j < 32; j++) { v[j] = e[j * 4096]; m = fmaxf(m, v[j]); }
    red[cg][ikl] = m;
    __syncthreads();
    float M = red[0][ikl];
    #pragma unroll
    for (int g = 1; g < 8; g++) M = fmaxf(M, red[g][ikl]);
    __syncthreads();

    float s = 0.f;
    #pragma unroll
    for (int j = 0; j < 32; j++) { v[j] = __expf(v[j] - M); s += v[j]; }
    red[cg][ikl] = s;
    __syncthreads();
    float S = red[0][ikl];
    #pragma unroll
    for (int g = 1; g < 8; g++) S += red[g][ikl];
    const float inv = 1.0f / S;

    __half* p = P + ((size_t)(b * 256 + cg * 32)) * 4096 + ik;
    #pragma unroll
    for (int j = 0; j < 32; j++) p[j * 4096] = __float2half(v[j] * inv);
}

// ---------------------------------------------------------------------------
// gemm2: O_c[i2,k2] = sum_j P_c[j,i2] * vT_c[k2,j]
// A: ldmatrix TRANS from P; B: ldmatrix non-trans from vT.
// ---------------------------------------------------------------------------
__global__ __launch_bounds__(128)
void attn_gemm2(const __half* __restrict__ P, const __half* __restrict__ vT,
                float* __restrict__ O)
{
    __shared__ __align__(16) __half Ps[64 * 72];
    __shared__ __align__(16) __half Vs[64 * 72];
    const int bc   = blockIdx.x;
    const int tid  = threadIdx.x;
    const int wid  = tid >> 5;
    const int lane = tid & 31;

    const __half* pg = P  + bc * 4096;
    const __half* vg = vT + bc * 4096;
    #pragma unroll
    for (int i = 0; i < 4; i++) {
        const int idx = tid + i * 128;
        const int r  = idx >> 3;
        const int c8 = idx & 7;
        *(uint4*)&Ps[r * 72 + c8 * 8] = *(const uint4*)&pg[r * 64 + c8 * 8];
        *(uint4*)&Vs[r * 72 + c8 * 8] = *(const uint4*)&vg[r * 64 + c8 * 8];
    }
    __syncthreads();

    float acc[8][4];
    #pragma unroll
    for (int i = 0; i < 8; i++)
        #pragma unroll
        for (int j = 0; j < 4; j++) acc[i][j] = 0.f;

    const int i0   = wid * 16;
    const int arow = (lane & 7) + ((lane & 16) ? 8 : 0);
    const int acol = i0 + ((lane & 8) ? 8 : 0);
    const int brow = (lane & 7) + ((lane & 16) ? 8 : 0);
    const int bcol = (lane & 8) ? 8 : 0;

    #pragma unroll
    for (int kp = 0; kp < 4; kp++) {                      // j chunks
        uint32_t a[4];
        ldsm4t(a, scvta(&Ps[(kp * 16 + arow) * 72 + acol]));
        #pragma unroll
        for (int np = 0; np < 4; np++) {                  // n chunks of 16
            uint32_t bf[4];
            ldsm4(bf, scvta(&Vs[(np * 16 + brow) * 72 + kp * 16 + bcol]));
            mma_f16(acc[np * 2 + 0], a, bf[0], bf[1]);
            mma_f16(acc[np * 2 + 1], a, bf[2], bf[3]);
        }
    }

    float* ob = O + bc * 4096;
    const int r0 = i0 + (lane >> 2);
    const int cb = (lane & 3) * 2;
    #pragma unroll
    for (int na = 0; na < 8; na++) {
        const int col = na * 8 + cb;
        *(float2*)&ob[r0 * 64 + col]       = make_float2(acc[na][0], acc[na][1]);
        *(float2*)&ob[(r0 + 8) * 64 + col] = make_float2(acc[na][2], acc[na][3]);
    }
}

// ---------------------------------------------------------------------------
// Final: out[b,ik,c] = gamma * O[b,c,ik] + x[b,ik,c]  (tile-transposed)
// smem row stride 68 floats = 272B (16B-aligned).
// ---------------------------------------------------------------------------
__global__ __launch_bounds__(256)
void final_merge(const float* __restrict__ O, const float* __restrict__ x,
                 const float* __restrict__ gammap, float* __restrict__ outp)
{
    __shared__ __align__(16) float t[64 * 68];
    const int b   = blockIdx.z;
    const int ik0 = blockIdx.x * 64;
    const int c0  = blockIdx.y * 64;
    const int tid = threadIdx.x;

    #pragma unroll
    for (int i = 0; i < 4; i++) {
        const int idx = tid + i * 256;         // float4 units (1024 total)
        const int r   = idx >> 4;              // c row
        const int c16 = idx & 15;
        *(float4*)&t[r * 68 + c16 * 4] =
            *(const float4*)&O[((size_t)(b * 256 + c0 + r)) * 4096 + ik0 + c16 * 4];
    }
    __syncthreads();

    const float gm = gammap[0];
    const int ik = tid & 63;
    const int cg = tid >> 6;                   // 4 groups of 16 c
    const int gbase = ((b * 4096) + ik0 + ik) * 256 + c0 + cg * 16;
    #pragma unroll
    for (int i = 0; i < 16; i += 4) {
        const int c = cg * 16 + i;
        const float4 xv = *(const float4*)&x[gbase + i];
        float4 o;
        o.x = gm * t[(c + 0) * 68 + ik] + xv.x;
        o.y = gm * t[(c + 1) * 68 + ik] + xv.y;
        o.z = gm * t[(c + 2) * 68 + ik] + xv.z;
        o.w = gm * t[(c + 3) * 68 + ik] + xv.w;
        *(float4*)&outp[gbase + i] = o;
    }
}

// ---------------------------------------------------------------------------
extern "C" void kernel_launch(void* const* d_in, const int* in_sizes, int n_in,
                              void* d_out, int out_size)
{
    const float* x    = (const float*)d_in[0];
    const float* wq   = (const float*)d_in[1];
    const float* bq   = (const float*)d_in[2];
    const float* wq1  = (const float*)d_in[3];
    const float* bq1  = (const float*)d_in[4];
    const float* wq2  = (const float*)d_in[5];
    const float* bq2  = (const float*)d_in[6];
    const float* wq3  = (const float*)d_in[7];
    const float* bq3  = (const float*)d_in[8];
    const float* wq4  = (const float*)d_in[9];
    const float* bq4  = (const float*)d_in[10];
    const float* wk   = (const float*)d_in[11];
    const float* bk   = (const float*)d_in[12];
    const float* wv   = (const float*)d_in[13];
    const float* bv   = (const float*)d_in[14];
    const float* gamma= (const float*)d_in[15];
    float* out = (float*)d_out;

    __half *xh, *k1h, *qcath, *kh, *qh, *vh, *kT, *qT, *vT, *P, *wt;
    float *E, *O;
    cudaGetSymbolAddress((void**)&xh,    g_xh);
    cudaGetSymbolAddress((void**)&k1h,   g_k1h);
    cudaGetSymbolAddress((void**)&qcath, g_qcath);
    cudaGetSymbolAddress((void**)&kh,    g_kh);
    cudaGetSymbolAddress((void**)&qh,    g_qh);
    cudaGetSymbolAddress((void**)&vh,    g_vh);
    cudaGetSymbolAddress((void**)&kT,    g_kT);
    cudaGetSymbolAddress((void**)&qT,    g_qT);
    cudaGetSymbolAddress((void**)&vT,    g_vT);
    cudaGetSymbolAddress((void**)&E,     g_E);
    cudaGetSymbolAddress((void**)&P,     g_P);
    cudaGetSymbolAddress((void**)&O,     g_O);
    cudaGetSymbolAddress((void**)&wt,    g_wt);

    const int SM256 = 3 * (128 + 128) * 20 * 4;   // 61440
    const int SM64  = 3 * (128 + 64)  * 20 * 4;   // 46080
    cudaFuncSetAttribute(conv_g<256,3,true>, cudaFuncAttributeMaxDynamicSharedMemorySize, SM256);
    cudaFuncSetAttribute(conv_g<256,1,true>, cudaFuncAttributeMaxDynamicSharedMemorySize, SM256);
    cudaFuncSetAttribute(conv_g<64,1,true>,  cudaFuncAttributeMaxDynamicSharedMemorySize, SM64);
    cudaFuncSetAttribute(qconv3_g,           cudaFuncAttributeMaxDynamicSharedMemorySize, SM64);

    const dim3 cblk(256);

    // pre-passes (fused: 2 launches)
    x2h_kernel<<<NELEM / 4 / 256, 256>>>(x, xh);
    wtrans_all<<<1179648 / 256, 256>>>(wk, wq4, wv, wq1, wq2, wq3, wq, wt);

    // convs (all fp16 out)
    conv_g<256,3,true><<<dim3(256,2), cblk, SM256>>>(xh,  wt + WT_WK, bk, k1h, 0, 256, 1);
    conv_g<256,3,true><<<dim3(256,2), cblk, SM256>>>(k1h, wt + WT_WK, bk, kh,  0, 256, 1);
    conv_g<64,1,true><<<dim3(256,1), cblk, SM64>>>(xh, wt + WT_WQ, bq, qcath, 0, 256, 1);
    qconv3_g<<<dim3(256,1,3), cblk, SM64>>>(xh, wt + WT_WQ1, bq1, bq2, bq3, qcath);
    conv_g<256,1,true><<<dim3(256,2), cblk, SM256>>>(qcath, wt + WT_WQ4, bq4, qh, 0, 256, 1);
    conv_g<256,1,true><<<dim3(256,2), cblk, SM256>>>(xh,    wt + WT_WV,  bv,  vh, 0, 256, 1);

    // attention (MMA path)
    transp3_h<<<dim3(64,4,24), 256>>>(kh, qh, vh, kT, qT, vT);
    attn_gemm1<<<2048, 128>>>(kT, qT, E);
    softmax_c_kernel<<<1024, 256>>>(E, P);
    attn_gemm2<<<2048, 128>>>(P, vT, O);
    final_merge<<<dim3(64,4,8), 256>>>(O, x, gamma, out);
}

// round 16
// speedup vs baseline: 7.8144x; 1.2251x over previous
#include <cuda_runtime.h>
#include <cuda_fp16.h>
#include <cstdint>
#include <cstring>

#define B_ 8
#define H_ 64
#define W_ 64
#define C_ 256
#define NPIXTOT (B_*H_*W_)
#define NELEM (NPIXTOT*C_)

// Scratch (device globals; no allocation allowed) — all 16B-aligned for uint4 access
__device__ __align__(16) __half g_xh[NELEM];     // fp16 input
__device__ __align__(16) __half g_k1h[NELEM];    // fp16 intermediate (k branch)
__device__ __align__(16) __half g_qcath[NELEM];  // fp16 concat (q branch)
__device__ __align__(16) __half g_kh[NELEM];     // conv outputs, (b,pix,c) fp16
__device__ __align__(16) __half g_qh[NELEM];
__device__ __align__(16) __half g_vh[NELEM];
__device__ __align__(16) __half g_kT[NELEM];     // channel-first (b,c,i,j) fp16
__device__ __align__(16) __half g_qT[NELEM];
__device__ __align__(16) __half g_vT[NELEM];
__device__ __align__(16) float  g_E[NELEM];      // energy (b,c,i,k) fp32
__device__ __align__(16) __half g_P[NELEM];      // softmaxed attention (b,c,i,k) fp16
__device__ __align__(16) float  g_O[NELEM];      // attn output (b,c,i,k) fp32
// transposed fp16 weights [cout][ktot]
__device__ __align__(16) __half g_wt[1179648];

#define WT_WK   0
#define WT_WQ4  589824
#define WT_WV   655360
#define WT_WQ1  720896
#define WT_WQ2  868352
#define WT_WQ3  1015808
#define WT_WQ   1163264

__device__ __forceinline__ uint32_t h2u(__half2 h) {
    uint32_t u; memcpy(&u, &h, 4); return u;
}

__device__ __forceinline__ void mma_f16(float* d, const uint32_t* a,
                                        uint32_t b0, uint32_t b1) {
    asm volatile(
        "mma.sync.aligned.m16n8k16.row.col.f32.f16.f16.f32 "
        "{%0,%1,%2,%3}, {%4,%5,%6,%7}, {%8,%9}, {%0,%1,%2,%3};"
        : "+f"(d[0]), "+f"(d[1]), "+f"(d[2]), "+f"(d[3])
        : "r"(a[0]), "r"(a[1]), "r"(a[2]), "r"(a[3]), "r"(b0), "r"(b1));
}
__device__ __forceinline__ void ldsm4(uint32_t* r, uint32_t addr) {
    asm volatile("ldmatrix.sync.aligned.m8n8.x4.shared.b16 {%0,%1,%2,%3}, [%4];"
        : "=r"(r[0]), "=r"(r[1]), "=r"(r[2]), "=r"(r[3]) : "r"(addr));
}
__device__ __forceinline__ void ldsm4t(uint32_t* r, uint32_t addr) {
    asm volatile("ldmatrix.sync.aligned.m8n8.x4.trans.shared.b16 {%0,%1,%2,%3}, [%4];"
        : "=r"(r[0]), "=r"(r[1]), "=r"(r[2]), "=r"(r[3]) : "r"(addr));
}
__device__ __forceinline__ uint32_t scvta(const void* p) {
    return (uint32_t)__cvta_generic_to_shared(p);
}
__device__ __forceinline__ void cp16(uint32_t saddr, const void* gaddr, uint32_t sz) {
    asm volatile("cp.async.ca.shared.global [%0], [%1], 16, %2;"
                 :: "r"(saddr), "l"(gaddr), "r"(sz) : "memory");
}
__device__ __forceinline__ void cp_commit() {
    asm volatile("cp.async.commit_group;" ::: "memory");
}
__device__ __forceinline__ void cp_wait1() {
    asm volatile("cp.async.wait_group 1;" ::: "memory");
}

// ---------------------------------------------------------------------------
// x -> fp16 pre-pass
// ---------------------------------------------------------------------------
__global__ __launch_bounds__(256)
void x2h_kernel(const float* __restrict__ x, __half* __restrict__ xh)
{
    const int i4 = blockIdx.x * 256 + threadIdx.x;
    const float4 v = *(const float4*)&x[i4 * 4];
    __half2* o = (__half2*)&xh[i4 * 4];
    o[0] = __floats2half2_rn(v.x, v.y);
    o[1] = __floats2half2_rn(v.z, v.w);
}

// ---------------------------------------------------------------------------
// ALL weight transposes fused: one segmented kernel.
// ---------------------------------------------------------------------------
__global__ __launch_bounds__(256)
void wtrans_all(const float* __restrict__ wk,  const float* __restrict__ wq4,
                const float* __restrict__ wv,  const float* __restrict__ wq1,
                const float* __restrict__ wq2, const float* __restrict__ wq3,
                const float* __restrict__ wq,  __half* __restrict__ wt)
{
    const int idx = blockIdx.x * 256 + threadIdx.x;   // < 1179648
    const float* src; int base, COUT, KTOT;
    if      (idx < 655360)  { if (idx < 589824) { src=wk;  base=0;       COUT=256; KTOT=2304; }
                              else              { src=wq4; base=589824;  COUT=256; KTOT=256;  } }
    else if (idx < 868352)  { if (idx < 720896) { src=wv;  base=655360;  COUT=256; KTOT=256;  }
                              else              { src=wq1; base=720896;  COUT=64;  KTOT=2304; } }
    else if (idx < 1163264) { if (idx < 1015808){ src=wq2; base=868352;  COUT=64;  KTOT=2304; }
                              else              { src=wq3; base=1015808; COUT=64;  KTOT=2304; } }
    else                    {                     src=wq;  base=1163264; COUT=64;  KTOT=256;  }
    const int l  = idx - base;
    const int co = l / KTOT;
    const int kk = l - co * KTOT;
    wt[idx] = __float2half_rn(src[kk * COUT + co]);
}

// ---------------------------------------------------------------------------
// Implicit-GEMM conv via mma.sync fp16 (m16n8k16), cp.async 3-stage pipeline.
// Fragment loads via ldmatrix (A non-trans, B non-trans n16 tiles).
// ---------------------------------------------------------------------------
template<int COUT, int KS, bool OUTH>
__device__ __forceinline__
void conv_body(const __half* __restrict__ x, const __half* __restrict__ wt,
               const float* __restrict__ bias, void* __restrict__ outp,
               int coff, int ctot, int dil, int tile, int n0)
{
    constexpr int KTOT   = KS * KS * 256;
    constexpr int NCH    = KS * KS * 8;
    constexpr int BN     = (COUT == 256) ? 128 : 64;
    constexpr int WN     = BN / 2;
    constexpr int NA     = WN / 8;
    constexpr int AST    = 20;                    // uint32 words per row
    constexpr int ASTH   = 40;                    // halves per row
    constexpr int AL     = 2;
    constexpr int BL     = BN / 64;
    constexpr int STAGES = 3;

    extern __shared__ uint32_t sm32[];
    uint32_t* Asm = sm32;
    uint32_t* Bsm = sm32 + STAGES * 128 * AST;

    const int tid  = threadIdx.x;
    const int wid  = tid >> 5;
    const int lane = tid & 31;
    const int wm   = wid >> 1;
    const int wn   = wid & 1;
    const int gr   = lane >> 2;
    const int gc   = lane & 3;

    const int b  = tile >> 5;
    const int h0 = (tile & 31) * 2;

    float acc[2][NA][4];
    #pragma unroll
    for (int am = 0; am < 2; am++)
        #pragma unroll
        for (int an = 0; an < NA; an++)
            #pragma unroll
            for (int i = 0; i < 4; i++) acc[am][an][i] = 0.f;

    auto issue = [&](int ch) {
        const int st  = ch % STAGES;
        const int tap = ch >> 3;
        const int c0  = (ch & 7) * 32;
        const int dy  = (tap / KS - KS / 2) * dil;
        const int dx  = (tap % KS - KS / 2) * dil;
        uint32_t* As = Asm + st * 128 * AST;
        uint32_t* Bs = Bsm + st * BN * AST;
        #pragma unroll
        for (int i = 0; i < AL; i++) {
            const int idx = tid + i * 256;
            const int row = idx >> 2;
            const int c16 = idx & 3;
            const int ph  = row >> 6;
            const int pw  = row & 63;
            const int h_in = h0 + ph + dy;
            const int w_in = pw + dx;
            const bool valid = ((unsigned)h_in < 64u) && ((unsigned)w_in < 64u);
            const __half* src = valid
                ? &x[(((b*64 + h_in)*64 + w_in) * 256) + c0 + c16*8] : x;
            cp16(scvta(&As[row * AST + c16 * 4]), src, valid ? 16u : 0u);
        }
        const int koff = tap * 256 + c0;
        #pragma unroll
        for (int i = 0; i < BL; i++) {
            const int idx = tid + i * 256;
            const int row = idx >> 2;
            const int c16 = idx & 3;
            cp16(scvta(&Bs[row * AST + c16 * 4]),
                 &wt[(n0 + row) * KTOT + koff + c16 * 8], 16u);
        }
        cp_commit();
    };

    // ldmatrix lane->address mappings (verified in attn_gemm1/attn_gemm2)
    const int arow = (lane & 7) + ((lane & 8) ? 8 : 0);
    const int acol = (lane & 16) ? 8 : 0;
    const int brow = (lane & 7) + ((lane & 16) ? 8 : 0);
    const int bcol = (lane & 8) ? 8 : 0;

    auto compute = [&](int st) {
        const __half* Ash = (const __half*)(Asm + st * 128 * AST);
        const __half* Bsh = (const __half*)(Bsm + st * BN * AST);
        #pragma unroll
        for (int s = 0; s < 2; s++) {
            uint32_t a[2][4];
            #pragma unroll
            for (int am = 0; am < 2; am++)
                ldsm4(a[am], scvta(&Ash[(wm*32 + am*16 + arow) * ASTH + s*16 + acol]));
            #pragma unroll
            for (int ng = 0; ng < NA/2; ng++) {
                uint32_t bf[4];
                ldsm4(bf, scvta(&Bsh[(wn*WN + ng*16 + brow) * ASTH + s*16 + bcol]));
                #pragma unroll
                for (int am = 0; am < 2; am++) {
                    mma_f16(acc[am][ng*2+0], a[am], bf[0], bf[1]);
                    mma_f16(acc[am][ng*2+1], a[am], bf[2], bf[3]);
                }
            }
        }
    };

    issue(0);
    issue(1);
    for (int ch = 0; ch < NCH; ch++) {
        cp_wait1();
        __syncthreads();   // all warps' copies for stage ch visible; also
                           // guarantees all warps passed compute(ch-1)
        if (ch + 2 < NCH) issue(ch + 2);   // overwrites buffer of compute(ch-1)
        else              cp_commit();
        compute(ch % STAGES);
    }

    #pragma unroll
    for (int am = 0; am < 2; am++) {
        #pragma unroll
        for (int an = 0; an < NA; an++) {
            const int cl = n0 + wn*WN + an*8 + gc*2;
            const float b0v = bias[cl];
            const float b1v = bias[cl + 1];
            #pragma unroll
            for (int half = 0; half < 2; half++) {
                const int mr = wm*32 + am*16 + gr + half*8;
                const int ph = mr >> 6;
                const int pw = mr & 63;
                const int base = (((b*64 + h0 + ph)*64 + pw) * ctot) + coff + cl;
                const float o0 = acc[am][an][half*2 + 0] + b0v;
                const float o1 = acc[am][an][half*2 + 1] + b1v;
                if (OUTH) {
                    *(__half2*)&((__half*)outp)[base] = __floats2half2_rn(o0, o1);
                } else {
                    *(float2*)&((float*)outp)[base] = make_float2(o0, o1);
                }
            }
        }
    }
}

template<int COUT, int KS, bool OUTH>
__global__ __launch_bounds__(256)
void conv_g(const __half* __restrict__ x, const __half* __restrict__ wt,
            const float* __restrict__ bias, void* __restrict__ out,
            int coff, int ctot, int dil)
{
    constexpr int BN = (COUT == 256) ? 128 : 64;
    conv_body<COUT, KS, OUTH>(x, wt, bias, out, coff, ctot, dil,
                              blockIdx.x, blockIdx.y * BN);
}

__global__ __launch_bounds__(256)
void qconv3_g(const __half* __restrict__ x, const __half* __restrict__ wt,
              const float* __restrict__ b1, const float* __restrict__ b2,
              const float* __restrict__ b3, __half* __restrict__ out)
{
    const int z = blockIdx.z;
    const int dil = (z == 0) ? 1 : ((z == 1) ? 3 : 6);
    const float* bias = (z == 0) ? b1 : ((z == 1) ? b2 : b3);
    conv_body<64, 3, true>(x, wt + z * 64 * 2304, bias, out,
                           64 + z * 64, 256, dil, blockIdx.x, 0);
}

// ---------------------------------------------------------------------------
// fp16 transpose, 3 tensors in one launch (z = tensor*8 + b)
// ---------------------------------------------------------------------------
__global__ __launch_bounds__(256)
void transp3_h(const __half* __restrict__ kh, const __half* __restrict__ qh,
               const __half* __restrict__ vh, __half* __restrict__ kT,
               __half* __restrict__ qT, __half* __restrict__ vT)
{
    __shared__ __align__(16) __half t[64 * 72];
    const int z  = blockIdx.z;
    const int tn = z >> 3;
    const int b  = z & 7;
    const __half* in   = (tn == 0) ? kh : ((tn == 1) ? qh : vh);
    __half*       outp = (tn == 0) ? kT : ((tn == 1) ? qT : vT);
    const int p0 = blockIdx.x * 64;
    const int c0 = blockIdx.y * 64;
    const int tid = threadIdx.x;

    #pragma unroll
    for (int i = 0; i < 2; i++) {
        const int idx = tid + i * 256;
        const int r  = idx >> 3;
        const int c8 = idx & 7;
        *(uint4*)&t[r * 72 + c8 * 8] =
            *(const uint4*)&in[((b * 4096) + p0 + r) * 256 + c0 + c8 * 8];
    }
    __syncthreads();

    const int c  = tid & 63;
    const int pg = tid >> 6;
    uint4 o0, o1;
    o0.x = h2u(__halves2half2(t[(pg*16+ 0)*72 + c], t[(pg*16+ 1)*72 + c]));
    o0.y = h2u(__halves2half2(t[(pg*16+ 2)*72 + c], t[(pg*16+ 3)*72 + c]));
    o0.z = h2u(__halves2half2(t[(pg*16+ 4)*72 + c], t[(pg*16+ 5)*72 + c]));
    o0.w = h2u(__halves2half2(t[(pg*16+ 6)*72 + c], t[(pg*16+ 7)*72 + c]));
    o1.x = h2u(__halves2half2(t[(pg*16+ 8)*72 + c], t[(pg*16+ 9)*72 + c]));
    o1.y = h2u(__halves2half2(t[(pg*16+10)*72 + c], t[(pg*16+11)*72 + c]));
    o1.z = h2u(__halves2half2(t[(pg*16+12)*72 + c], t[(pg*16+13)*72 + c]));
    o1.w = h2u(__halves2half2(t[(pg*16+14)*72 + c], t[(pg*16+15)*72 + c]));
    __half* o = &outp[((b * 256) + c0 + c) * 4096 + p0 + pg * 16];
    *(uint4*)&o[0] = o0;
    *(uint4*)&o[8] = o1;
}

// ---------------------------------------------------------------------------
// gemm1: E_c[i,k2] = sum_j kT_c[i,j] * qT_c[j,k2]   (per b,c: 64x64x64)
// ---------------------------------------------------------------------------
__global__ __launch_bounds__(128)
void attn_gemm1(const __half* __restrict__ kT, const __half* __restrict__ qT,
                float* __restrict__ E)
{
    __shared__ __align__(16) __half Ks[64 * 72];
    __shared__ __align__(16) __half Qs[64 * 72];
    const int bc   = blockIdx.x;
    const int tid  = threadIdx.x;
    const int wid  = tid >> 5;
    const int lane = tid & 31;

    const __half* kg = kT + bc * 4096;
    const __half* qg = qT + bc * 4096;
    #pragma unroll
    for (int i = 0; i < 4; i++) {
        const int idx = tid + i * 128;
        const int r  = idx >> 3;
        const int c8 = idx & 7;
        *(uint4*)&Ks[r * 72 + c8 * 8] = *(const uint4*)&kg[r * 64 + c8 * 8];
        *(uint4*)&Qs[r * 72 + c8 * 8] = *(const uint4*)&qg[r * 64 + c8 * 8];
    }
    __syncthreads();

    float acc[8][4];
    #pragma unroll
    for (int i = 0; i < 8; i++)
        #pragma unroll
        for (int j = 0; j < 4; j++) acc[i][j] = 0.f;

    const int i0   = wid * 16;
    const int arow = (lane & 7) + ((lane & 8) ? 8 : 0);
    const int acol = (lane & 16) ? 8 : 0;
    const int brow = (lane & 7) + ((lane & 8) ? 8 : 0);
    const int bcol = (lane & 16) ? 8 : 0;

    #pragma unroll
    for (int kp = 0; kp < 4; kp++) {
        uint32_t a[4];
        ldsm4(a, scvta(&Ks[(i0 + arow) * 72 + kp * 16 + acol]));
        #pragma unroll
        for (int np = 0; np < 4; np++) {
            uint32_t bf[4];
            ldsm4t(bf, scvta(&Qs[(kp * 16 + brow) * 72 + np * 16 + bcol]));
            mma_f16(acc[np * 2 + 0], a, bf[0], bf[1]);
            mma_f16(acc[np * 2 + 1], a, bf[2], bf[3]);
        }
    }

    float* eb = E + bc * 4096;
    const int r0 = i0 + (lane >> 2);
    const int cb = (lane & 3) * 2;
    #pragma unroll
    for (int na = 0; na < 8; na++) {
        const int col = na * 8 + cb;
        *(float2*)&eb[r0 * 64 + col]       = make_float2(acc[na][0], acc[na][1]);
        *(float2*)&eb[(r0 + 8) * 64 + col] = make_float2(acc[na][2], acc[na][3]);
    }
}

// ---------------------------------------------------------------------------
// Softmax over channel axis, block-cooperative (8 c-groups x 32 ik / block)
// ---------------------------------------------------------------------------
__global__ __launch_bounds__(256)
void softmax_c_kernel(const float* __restrict__ E, __half* __restrict__ P)
{
    __shared__ float red[8][32];
    const int b   = blockIdx.x >> 7;
    const int ik0 = (blockIdx.x & 127) * 32;
    const int ikl = threadIdx.x & 31;
    const int cg  = threadIdx.x >> 5;
    const int ik  = ik0 + ikl;

    const float* e = E + ((size_t)(b * 256 + cg * 32)) * 4096 + ik;
    float v[32];
    float m = -1e30f;
    #pragma unroll
    for (int j = 0; j < 32; j++) { v[j] = e[j * 4096]; m = fmaxf(m, v[j]); }
    red[cg][ikl] = m;
    __syncthreads();
    float M = red[0][ikl];
    #pragma unroll
    for (int g = 1; g < 8; g++) M = fmaxf(M, red[g][ikl]);
    __syncthreads();

    float s = 0.f;
    #pragma unroll
    for (int j = 0; j < 32; j++) { v[j] = __expf(v[j] - M); s += v[j]; }
    red[cg][ikl] = s;
    __syncthreads();
    float S = red[0][ikl];
    #pragma unroll
    for (int g = 1; g < 8; g++) S += red[g][ikl];
    const float inv = 1.0f / S;

    __half* p = P + ((size_t)(b * 256 + cg * 32)) * 4096 + ik;
    #pragma unroll
    for (int j = 0; j < 32; j++) p[j * 4096] = __float2half(v[j] * inv);
}

// ---------------------------------------------------------------------------
// gemm2: O_c[i2,k2] = sum_j P_c[j,i2] * vT_c[k2,j]
// ---------------------------------------------------------------------------
__global__ __launch_bounds__(128)
void attn_gemm2(const __half* __restrict__ P, const __half* __restrict__ vT,
                float* __restrict__ O)
{
    __shared__ __align__(16) __half Ps[64 * 72];
    __shared__ __align__(16) __half Vs[64 * 72];
    const int bc   = blockIdx.x;
    const int tid  = threadIdx.x;
    const int wid  = tid >> 5;
    const int lane = tid & 31;

    const __half* pg = P  + bc * 4096;
    const __half* vg = vT + bc * 4096;
    #pragma unroll
    for (int i = 0; i < 4; i++) {
        const int idx = tid + i * 128;
        const int r  = idx >> 3;
        const int c8 = idx & 7;
        *(uint4*)&Ps[r * 72 + c8 * 8] = *(const uint4*)&pg[r * 64 + c8 * 8];
        *(uint4*)&Vs[r * 72 + c8 * 8] = *(const uint4*)&vg[r * 64 + c8 * 8];
    }
    __syncthreads();

    float acc[8][4];
    #pragma unroll
    for (int i = 0; i < 8; i++)
        #pragma unroll
        for (int j = 0; j < 4; j++) acc[i][j] = 0.f;

    const int i0   = wid * 16;
    const int arow = (lane & 7) + ((lane & 16) ? 8 : 0);
    const int acol = i0 + ((lane & 8) ? 8 : 0);
    const int brow = (lane & 7) + ((lane & 16) ? 8 : 0);
    const int bcol = (lane & 8) ? 8 : 0;

    #pragma unroll
    for (int kp = 0; kp < 4; kp++) {
        uint32_t a[4];
        ldsm4t(a, scvta(&Ps[(kp * 16 + arow) * 72 + acol]));
        #pragma unroll
        for (int np = 0; np < 4; np++) {
            uint32_t bf[4];
            ldsm4(bf, scvta(&Vs[(np * 16 + brow) * 72 + kp * 16 + bcol]));
            mma_f16(acc[np * 2 + 0], a, bf[0], bf[1]);
            mma_f16(acc[np * 2 + 1], a, bf[2], bf[3]);
        }
    }

    float* ob = O + bc * 4096;
    const int r0 = i0 + (lane >> 2);
    const int cb = (lane & 3) * 2;
    #pragma unroll
    for (int na = 0; na < 8; na++) {
        const int col = na * 8 + cb;
        *(float2*)&ob[r0 * 64 + col]       = make_float2(acc[na][0], acc[na][1]);
        *(float2*)&ob[(r0 + 8) * 64 + col] = make_float2(acc[na][2], acc[na][3]);
    }
}

// ---------------------------------------------------------------------------
// Final: out[b,ik,c] = gamma * O[b,c,ik] + x[b,ik,c]  (tile-transposed)
// ---------------------------------------------------------------------------
__global__ __launch_bounds__(256)
void final_merge(const float* __restrict__ O, const float* __restrict__ x,
                 const float* __restrict__ gammap, float* __restrict__ outp)
{
    __shared__ __align__(16) float t[64 * 68];
    const int b   = blockIdx.z;
    const int ik0 = blockIdx.x * 64;
    const int c0  = blockIdx.y * 64;
    const int tid = threadIdx.x;

    #pragma unroll
    for (int i = 0; i < 4; i++) {
        const int idx = tid + i * 256;
        const int r   = idx >> 4;
        const int c16 = idx & 15;
        *(float4*)&t[r * 68 + c16 * 4] =
            *(const float4*)&O[((size_t)(b * 256 + c0 + r)) * 4096 + ik0 + c16 * 4];
    }
    __syncthreads();

    const float gm = gammap[0];
    const int ik = tid & 63;
    const int cg = tid >> 6;
    const int gbase = ((b * 4096) + ik0 + ik) * 256 + c0 + cg * 16;
    #pragma unroll
    for (int i = 0; i < 16; i += 4) {
        const int c = cg * 16 + i;
        const float4 xv = *(const float4*)&x[gbase + i];
        float4 o;
        o.x = gm * t[(c + 0) * 68 + ik] + xv.x;
        o.y = gm * t[(c + 1) * 68 + ik] + xv.y;
        o.z = gm * t[(c + 2) * 68 + ik] + xv.z;
        o.w = gm * t[(c + 3) * 68 + ik] + xv.w;
        *(float4*)&outp[gbase + i] = o;
    }
}

// ---------------------------------------------------------------------------
extern "C" void kernel_launch(void* const* d_in, const int* in_sizes, int n_in,
                              void* d_out, int out_size)
{
    const float* x    = (const float*)d_in[0];
    const float* wq   = (const float*)d_in[1];
    const float* bq   = (const float*)d_in[2];
    const float* wq1  = (const float*)d_in[3];
    const float* bq1  = (const float*)d_in[4];
    const float* wq2  = (const float*)d_in[5];
    const float* bq2  = (const float*)d_in[6];
    const float* wq3  = (const float*)d_in[7];
    const float* bq3  = (const float*)d_in[8];
    const float* wq4  = (const float*)d_in[9];
    const float* bq4  = (const float*)d_in[10];
    const float* wk   = (const float*)d_in[11];
    const float* bk   = (const float*)d_in[12];
    const float* wv   = (const float*)d_in[13];
    const float* bv   = (const float*)d_in[14];
    const float* gamma= (const float*)d_in[15];
    float* out = (float*)d_out;

    __half *xh, *k1h, *qcath, *kh, *qh, *vh, *kT, *qT, *vT, *P, *wt;
    float *E, *O;
    cudaGetSymbolAddress((void**)&xh,    g_xh);
    cudaGetSymbolAddress((void**)&k1h,   g_k1h);
    cudaGetSymbolAddress((void**)&qcath, g_qcath);
    cudaGetSymbolAddress((void**)&kh,    g_kh);
    cudaGetSymbolAddress((void**)&qh,    g_qh);
    cudaGetSymbolAddress((void**)&vh,    g_vh);
    cudaGetSymbolAddress((void**)&kT,    g_kT);
    cudaGetSymbolAddress((void**)&qT,    g_qT);
    cudaGetSymbolAddress((void**)&vT,    g_vT);
    cudaGetSymbolAddress((void**)&E,     g_E);
    cudaGetSymbolAddress((void**)&P,     g_P);
    cudaGetSymbolAddress((void**)&O,     g_O);
    cudaGetSymbolAddress((void**)&wt,    g_wt);

    const int SM256 = 3 * (128 + 128) * 20 * 4;   // 61440
    const int SM64  = 3 * (128 + 64)  * 20 * 4;   // 46080
    cudaFuncSetAttribute(conv_g<256,3,true>, cudaFuncAttributeMaxDynamicSharedMemorySize, SM256);
    cudaFuncSetAttribute(conv_g<256,1,true>, cudaFuncAttributeMaxDynamicSharedMemorySize, SM256);
    cudaFuncSetAttribute(conv_g<64,1,true>,  cudaFuncAttributeMaxDynamicSharedMemorySize, SM64);
    cudaFuncSetAttribute(qconv3_g,           cudaFuncAttributeMaxDynamicSharedMemorySize, SM64);

    const dim3 cblk(256);

    // pre-passes (fused: 2 launches)
    x2h_kernel<<<NELEM / 4 / 256, 256>>>(x, xh);
    wtrans_all<<<1179648 / 256, 256>>>(wk, wq4, wv, wq1, wq2, wq3, wq, wt);

    // convs (all fp16 out)
    conv_g<256,3,true><<<dim3(256,2), cblk, SM256>>>(xh,  wt + WT_WK, bk, k1h, 0, 256, 1);
    conv_g<256,3,true><<<dim3(256,2), cblk, SM256>>>(k1h, wt + WT_WK, bk, kh,  0, 256, 1);
    conv_g<64,1,true><<<dim3(256,1), cblk, SM64>>>(xh, wt + WT_WQ, bq, qcath, 0, 256, 1);
    qconv3_g<<<dim3(256,1,3), cblk, SM64>>>(xh, wt + WT_WQ1, bq1, bq2, bq3, qcath);
    conv_g<256,1,true><<<dim3(256,2), cblk, SM256>>>(qcath, wt + WT_WQ4, bq4, qh, 0, 256, 1);
    conv_g<256,1,true><<<dim3(256,2), cblk, SM256>>>(xh,    wt + WT_WV,  bv,  vh, 0, 256, 1);

    // attention (MMA path)
    transp3_h<<<dim3(64,4,24), 256>>>(kh, qh, vh, kT, qT, vT);
    attn_gemm1<<<2048, 128>>>(kT, qT, E);
    softmax_c_kernel<<<1024, 256>>>(E, P);
    attn_gemm2<<<2048, 128>>>(P, vT, O);
    final_merge<<<dim3(64,4,8), 256>>>(O, x, gamma, out);
}